// round 3
// baseline (speedup 1.0000x reference)
#include <cuda_runtime.h>

// Shapes (fixed by the problem)
#define BB 32
#define AA 32
#define SS 128
#define DD 1024
#define NH 1024            // N*H = 16*64
#define ROWS (BB*AA)       // 1024
#define ENC_ROW_STRIDE ((size_t)SS * DD)   // 131072 floats between CLS rows

// Scratch (allocation-free rule: __device__ globals)
__device__ float g_Q[ROWS * NH];
__device__ float g_K[ROWS * NH];

#define TILE 128
#define BK   16
#define PAD  132   // smem row stride (floats), multiple of 4 for float4 alignment

// C[r, cGlobal] over r in [0,1024), cGlobal in [0,2048): cols [0,1024)=Q (WQ), [1024,2048)=K (WK)
__global__ void __launch_bounds__(256, 1)
gemm_qk_kernel(const float* __restrict__ enc,
               const int*   __restrict__ mask,
               const float* __restrict__ wq, const float* __restrict__ bq,
               const float* __restrict__ wk, const float* __restrict__ bk)
{
    const int tileR = blockIdx.y * TILE;          // 0..896
    const bool isK  = (blockIdx.x >= (NH / TILE));
    const int  c0   = (blockIdx.x - (isK ? (NH / TILE) : 0)) * TILE;  // 0..896 within Q or K
    const float* __restrict__ W    = isK ? wk : wq;
    const float* __restrict__ bias = isK ? bk : bq;
    float* __restrict__ outp = isK ? g_K : g_Q;

    __shared__ float As[BK][PAD];   // transposed: As[k][row]
    __shared__ float Bs[BK][PAD];   // Bs[k][col]

    const int tid = threadIdx.x;          // 256 threads
    const int tx  = tid & 15;             // col group: cols tx*8 .. tx*8+7
    const int ty  = tid >> 4;             // row group: rows ty*8 .. ty*8+7

    // 8x8 accumulator as 8x4 packed f32x2 (pairs along columns)
    unsigned long long acc[8][4];
#pragma unroll
    for (int i = 0; i < 8; i++)
#pragma unroll
        for (int j = 0; j < 4; j++) acc[i][j] = 0ull;

    for (int k0 = 0; k0 < DD; k0 += BK) {
        // --- load A tile (128 rows x 16 k) as float4, store transposed ---
#pragma unroll
        for (int i = 0; i < 2; i++) {
            int idx = tid + i * 256;          // 0..511
            int r   = idx >> 2;               // 0..127
            int cc  = (idx & 3) * 4;          // k-chunk 0,4,8,12
            float4 v = *reinterpret_cast<const float4*>(
                &enc[(size_t)(tileR + r) * ENC_ROW_STRIDE + (k0 + cc)]);
            As[cc + 0][r] = v.x;
            As[cc + 1][r] = v.y;
            As[cc + 2][r] = v.z;
            As[cc + 3][r] = v.w;
        }
        // --- load B tile (16 k x 128 cols) as float4 ---
#pragma unroll
        for (int i = 0; i < 2; i++) {
            int idx = tid + i * 256;          // 0..511
            int kk  = idx >> 5;               // 0..15
            int cc  = (idx & 31) * 4;         // 0..124
            float4 v = *reinterpret_cast<const float4*>(
                &W[(size_t)(k0 + kk) * NH + (c0 + cc)]);
            *reinterpret_cast<float4*>(&Bs[kk][cc]) = v;
        }
        __syncthreads();

#pragma unroll
        for (int kk = 0; kk < BK; kk++) {
            float4 a0 = *reinterpret_cast<const float4*>(&As[kk][ty * 8]);
            float4 a1 = *reinterpret_cast<const float4*>(&As[kk][ty * 8 + 4]);
            ulonglong2 bv0 = *reinterpret_cast<const ulonglong2*>(&Bs[kk][tx * 8]);
            ulonglong2 bv1 = *reinterpret_cast<const ulonglong2*>(&Bs[kk][tx * 8 + 4]);
            unsigned long long bb[4] = {bv0.x, bv0.y, bv1.x, bv1.y};
            float av[8] = {a0.x, a0.y, a0.z, a0.w, a1.x, a1.y, a1.z, a1.w};
#pragma unroll
            for (int i = 0; i < 8; i++) {
                unsigned long long a2;
                unsigned int ar = __float_as_uint(av[i]);
                asm("mov.b64 %0, {%1, %1};" : "=l"(a2) : "r"(ar));
#pragma unroll
                for (int j = 0; j < 4; j++) {
                    asm("fma.rn.f32x2 %0, %1, %2, %3;"
                        : "=l"(acc[i][j])
                        : "l"(a2), "l"(bb[j]), "l"(acc[i][j]));
                }
            }
        }
        __syncthreads();
    }

    // Epilogue: + bias, * mask, store
#pragma unroll
    for (int i = 0; i < 8; i++) {
        int r = tileR + ty * 8 + i;
        float m = (float)mask[r];
#pragma unroll
        for (int j = 0; j < 4; j++) {
            float2 v = *reinterpret_cast<float2*>(&acc[i][j]);
            int c = c0 + tx * 8 + j * 2;
            float2 o;
            o.x = (v.x + bias[c + 0]) * m;
            o.y = (v.y + bias[c + 1]) * m;
            *reinterpret_cast<float2*>(&outp[(size_t)r * NH + c]) = o;
        }
    }
}

// One block per batch b: Ksum, logits via  dot(Q[x], Ksum - K[x]), softmax over 32 docs
__global__ void __launch_bounds__(256, 1)
reduce_softmax_kernel(const int* __restrict__ mask, float* __restrict__ out)
{
    const int b = blockIdx.x;
    __shared__ float ksum[NH];
    __shared__ float logits[AA];

    const int tid = threadIdx.x;   // 256

    // Phase 1: Ksum[d] = sum_a K[b,a,d]
#pragma unroll
    for (int j = 0; j < 4; j++) {
        int d = tid + j * 256;
        float s = 0.f;
#pragma unroll 8
        for (int a = 0; a < AA; a++)
            s += g_K[(size_t)(b * AA + a) * NH + d];
        ksum[d] = s;
    }
    __syncthreads();

    // Phase 2: logits[x] = dot(Q[b,x], ksum - K[b,x]); warp w handles x = w, w+8, w+16, w+24
    const int warp = tid >> 5;
    const int lane = tid & 31;
#pragma unroll
    for (int xi = 0; xi < 4; xi++) {
        int x = warp + xi * 8;
        const float* qrow = &g_Q[(size_t)(b * AA + x) * NH];
        const float* krow = &g_K[(size_t)(b * AA + x) * NH];
        float s = 0.f;
#pragma unroll 8
        for (int d = lane; d < NH; d += 32)
            s += qrow[d] * (ksum[d] - krow[d]);
#pragma unroll
        for (int o = 16; o > 0; o >>= 1)
            s += __shfl_xor_sync(0xffffffffu, s, o);
        if (lane == 0) logits[x] = s;
    }
    __syncthreads();

    // Phase 3: softmax over 32 docs (warp 0)
    if (tid < 32) {
        float m = (float)mask[b * AA + tid];
        float l = logits[tid] + (1.0f - m) * -100000.0f;
        float mx = l;
#pragma unroll
        for (int o = 16; o > 0; o >>= 1)
            mx = fmaxf(mx, __shfl_xor_sync(0xffffffffu, mx, o));
        float e = expf(l - mx);
        float se = e;
#pragma unroll
        for (int o = 16; o > 0; o >>= 1)
            se += __shfl_xor_sync(0xffffffffu, se, o);
        out[b * AA + tid] = e / se;
    }
}

extern "C" void kernel_launch(void* const* d_in, const int* in_sizes, int n_in,
                              void* d_out, int out_size)
{
    const float* enc  = (const float*)d_in[0];   // (32,32,128,1024) f32
    const int*   mask = (const int*)  d_in[1];   // (32,32) i32
    const float* wq   = (const float*)d_in[2];   // (1024,16,64) f32
    const float* bq   = (const float*)d_in[3];   // (16,64) f32
    const float* wk   = (const float*)d_in[4];   // (1024,16,64) f32
    const float* bk   = (const float*)d_in[5];   // (16,64) f32
    float* out = (float*)d_out;                  // (32,32) f32

    dim3 grid(2 * NH / TILE, ROWS / TILE);       // (16, 8) = 128 CTAs
    gemm_qk_kernel<<<grid, 256>>>(enc, mask, wq, bq, wk, bk);
    reduce_softmax_kernel<<<BB, 256>>>(mask, out);
}

// round 5
// speedup vs baseline: 1.4814x; 1.4814x over previous
#include <cuda_runtime.h>
#include <cuda_bf16.h>
#include <cstdint>

// ---------------- problem shapes ----------------
#define BB 32
#define AA 32
#define SSQ 128
#define DD 1024
#define NHQ 1024                   // N*H
#define COLS2 2048                 // Q cols + K cols
#define ROWS 1024                  // B*A
#define ENC_ROW_STRIDE ((size_t)SSQ * DD)

// ---------------- device scratch (no allocs allowed) ----------------
__device__ __nv_bfloat16 g_A3[3][ROWS * DD];     // [comp][row][k]   (CLS splits)
__device__ __nv_bfloat16 g_B3[3][COLS2 * DD];    // [comp][col][k]   (W^T splits)
__device__ float g_Q[ROWS * NHQ];
__device__ float g_K[ROWS * NHQ];
__device__ float g_ksum[BB * NHQ];

// ---------------- split helper ----------------
__device__ __forceinline__ void split3(float x, __nv_bfloat16& h, __nv_bfloat16& m, __nv_bfloat16& l) {
    h = __float2bfloat16_rn(x);
    float r1 = x - __bfloat162float(h);
    m = __float2bfloat16_rn(r1);
    float r2 = r1 - __bfloat162float(m);
    l = __float2bfloat16_rn(r2);
}

// ---------------- kernel 1: split CLS rows into 3 bf16 planes ----------------
__global__ void split_cls_kernel(const float* __restrict__ enc) {
    int r = blockIdx.x;
    int j = threadIdx.x;               // 256 threads, one float4 each (DD/4 = 256)
    float4 v = reinterpret_cast<const float4*>(enc + (size_t)r * ENC_ROW_STRIDE)[j];
    float xs[4] = {v.x, v.y, v.z, v.w};
    ushort4 ph, pm, pl;
    unsigned short* hp = &ph.x; unsigned short* mp = &pm.x; unsigned short* lp = &pl.x;
#pragma unroll
    for (int i = 0; i < 4; i++) {
        __nv_bfloat16 h, m, l;
        split3(xs[i], h, m, l);
        hp[i] = __bfloat16_as_ushort(h);
        mp[i] = __bfloat16_as_ushort(m);
        lp[i] = __bfloat16_as_ushort(l);
    }
    size_t o = (size_t)r * DD + j * 4;
    *reinterpret_cast<ushort4*>(&g_A3[0][o]) = ph;
    *reinterpret_cast<ushort4*>(&g_A3[1][o]) = pm;
    *reinterpret_cast<ushort4*>(&g_A3[2][o]) = pl;
}

// ---------------- kernel 2: split + transpose W ([d][n] -> [col][k]) ----------------
__global__ void split_w_kernel(const float* __restrict__ wq, const float* __restrict__ wk) {
    __shared__ __nv_bfloat16 sh[3][32][33];
    int c0 = blockIdx.x * 32;          // global col tile (0..2047)
    int d0 = blockIdx.y * 32;
    int tx = threadIdx.x & 31;
    int ty = threadIdx.x >> 5;         // 0..7
    const float* W = (c0 < NHQ) ? wq : wk;
    int nb = (c0 < NHQ) ? c0 : (c0 - NHQ);
#pragma unroll
    for (int i = 0; i < 4; i++) {
        int dl = ty + i * 8;
        float x = W[(size_t)(d0 + dl) * NHQ + nb + tx];
        __nv_bfloat16 h, m, l;
        split3(x, h, m, l);
        sh[0][tx][dl] = h;             // [n_local][d_local]
        sh[1][tx][dl] = m;
        sh[2][tx][dl] = l;
    }
    __syncthreads();
#pragma unroll
    for (int i = 0; i < 4; i++) {
        int nl = ty + i * 8;
        size_t o = (size_t)(c0 + nl) * DD + d0 + tx;
        g_B3[0][o] = sh[0][nl][tx];
        g_B3[1][o] = sh[1][nl][tx];
        g_B3[2][o] = sh[2][nl][tx];
    }
}

// ---------------- kernel 3: mma.sync bf16 GEMM, 3-split x 6 products ----------------
// CTA tile 128x128, K-chunk 64, 8 warps of 64x32 warp tiles, cp.async double buffer.
#define KC 64
#define NCHUNK (DD / KC)                     // 16
#define RSTR 72                              // smem row stride in bf16 (conflict-free: (4g+t)%32)
#define PLANE_E (128 * RSTR)                 // 9216 bf16 per plane
#define STAGE_E (6 * PLANE_E)                // 55296 bf16 per stage
#define STAGE_B (STAGE_E * 2)                // 110592 bytes
#define SMEM_TOTAL (2 * STAGE_B)             // 221184 bytes

__device__ __forceinline__ uint32_t smem_u32(const void* p) {
    uint32_t a;
    asm("{ .reg .u64 t; cvta.to.shared.u64 t, %1; cvt.u32.u64 %0, t; }" : "=r"(a) : "l"(p));
    return a;
}
#define CP_ASYNC16(dst, src) \
    asm volatile("cp.async.cg.shared.global [%0], [%1], 16;" :: "r"(dst), "l"(src) : "memory")
#define CP_COMMIT() asm volatile("cp.async.commit_group;" ::: "memory")
#define CP_WAIT(N)  asm volatile("cp.async.wait_group %0;" :: "n"(N) : "memory")

__device__ __forceinline__ void mma_bf16(float* c, const uint32_t* a, const uint32_t* b) {
    asm volatile(
        "mma.sync.aligned.m16n8k16.row.col.f32.bf16.bf16.f32 "
        "{%0,%1,%2,%3}, {%4,%5,%6,%7}, {%8,%9}, {%0,%1,%2,%3};"
        : "+f"(c[0]), "+f"(c[1]), "+f"(c[2]), "+f"(c[3])
        : "r"(a[0]), "r"(a[1]), "r"(a[2]), "r"(a[3]), "r"(b[0]), "r"(b[1]));
}

__device__ __forceinline__ void load_stage_async(uint32_t st_b, int tid, int tileR, int c0, int k0) {
#pragma unroll
    for (int it = 0; it < 24; it++) {
        int idx = tid + it * 256;            // 0..6143
        int t   = idx >> 10;                 // plane 0..5
        int e   = idx & 1023;
        int row = e >> 3;                    // 0..127
        int seg = e & 7;                     // 16B segment in the 128B row payload
        const __nv_bfloat16* gsrc = (t < 3)
            ? &g_A3[t][(size_t)(tileR + row) * DD + k0 + seg * 8]
            : &g_B3[t - 3][(size_t)(c0 + row) * DD + k0 + seg * 8];
        uint32_t dst = st_b + (uint32_t)t * (PLANE_E * 2) + (uint32_t)row * (RSTR * 2) + seg * 16;
        CP_ASYNC16(dst, (const void*)__cvta_generic_to_global(gsrc));
    }
    CP_COMMIT();
}

__global__ void __launch_bounds__(256, 1)
gemm_mma_kernel(const float* __restrict__ bq, const float* __restrict__ bk,
                const int* __restrict__ mask)
{
    extern __shared__ __nv_bfloat16 smem[];   // 2 stages
    const uint32_t sb = smem_u32(smem);

    const int tid = threadIdx.x;
    const int wid = tid >> 5, lane = tid & 31;
    const int g = lane >> 2, t = lane & 3;    // mma group / thread-in-group
    const int wr = wid >> 2;                  // 0..1 -> m offset wr*64
    const int wc = wid & 3;                   // 0..3 -> n offset wc*32
    const int tileR = blockIdx.y * 128;
    const int c0 = blockIdx.x * 128;          // global col in [0,2048)

    float acc[4][4][4];                       // [mt][nt][reg]
#pragma unroll
    for (int i = 0; i < 4; i++)
#pragma unroll
        for (int j = 0; j < 4; j++)
#pragma unroll
            for (int r = 0; r < 4; r++) acc[i][j][r] = 0.f;

    // product order (pa,pb), small terms first
    const int PA[6] = {2, 0, 1, 1, 0, 0};
    const int PB[6] = {0, 2, 1, 0, 1, 0};

    load_stage_async(sb, tid, tileR, c0, 0);

    for (int c = 0; c < NCHUNK; c++) {
        const uint32_t stg = sb + (uint32_t)(c & 1) * STAGE_B;
        if (c + 1 < NCHUNK)
            load_stage_async(sb + (uint32_t)((c + 1) & 1) * STAGE_B, tid, tileR, c0, (c + 1) * KC);
        if (c + 1 < NCHUNK) { CP_WAIT(1); } else { CP_WAIT(0); }
        __syncthreads();

        const __nv_bfloat16* s = smem + (size_t)(c & 1) * STAGE_E;
#pragma unroll
        for (int ks = 0; ks < 4; ks++) {
            uint32_t afr[3][4][4];
            uint32_t bfr[3][4][2];
#pragma unroll
            for (int p = 0; p < 3; p++) {
#pragma unroll
                for (int mt = 0; mt < 4; mt++) {
                    int rb = wr * 64 + mt * 16;
                    const uint32_t* r0 = reinterpret_cast<const uint32_t*>(
                        s + p * PLANE_E + (rb + g) * RSTR + ks * 16 + t * 2);
                    const uint32_t* r1 = reinterpret_cast<const uint32_t*>(
                        s + p * PLANE_E + (rb + g + 8) * RSTR + ks * 16 + t * 2);
                    afr[p][mt][0] = r0[0];     // (g,     k..k+1)
                    afr[p][mt][1] = r1[0];     // (g+8,   k..k+1)
                    afr[p][mt][2] = r0[4];     // (g,   k+8..k+9)
                    afr[p][mt][3] = r1[4];     // (g+8, k+8..k+9)
                }
#pragma unroll
                for (int nt = 0; nt < 4; nt++) {
                    int rb = wc * 32 + nt * 8;
                    const uint32_t* r0 = reinterpret_cast<const uint32_t*>(
                        s + (3 + p) * PLANE_E + (rb + g) * RSTR + ks * 16 + t * 2);
                    bfr[p][nt][0] = r0[0];     // (n=g, k..k+1)
                    bfr[p][nt][1] = r0[4];     // (n=g, k+8..k+9)
                }
            }
#pragma unroll
            for (int j = 0; j < 6; j++) {
#pragma unroll
                for (int mt = 0; mt < 4; mt++)
#pragma unroll
                    for (int nt = 0; nt < 4; nt++)
                        mma_bf16(acc[mt][nt], afr[PA[j]][mt], bfr[PB[j]][nt]);
            }
        }
        __syncthreads();
    }

    // ---------------- epilogue: + bias, * mask, store ----------------
    const bool isK = (c0 >= NHQ);
    float* __restrict__ outp = isK ? g_K : g_Q;
    const float* __restrict__ bias = isK ? bk : bq;
    const int cb = isK ? (c0 - NHQ) : c0;

#pragma unroll
    for (int mt = 0; mt < 4; mt++) {
        int r0 = tileR + wr * 64 + mt * 16 + g;
        int r1 = r0 + 8;
        float m0 = (float)mask[r0];
        float m1 = (float)mask[r1];
#pragma unroll
        for (int nt = 0; nt < 4; nt++) {
            int col = cb + wc * 32 + nt * 8 + t * 2;
            float b0 = bias[col], b1 = bias[col + 1];
            float2 o0, o1;
            o0.x = (acc[mt][nt][0] + b0) * m0;
            o0.y = (acc[mt][nt][1] + b1) * m0;
            o1.x = (acc[mt][nt][2] + b0) * m1;
            o1.y = (acc[mt][nt][3] + b1) * m1;
            *reinterpret_cast<float2*>(&outp[(size_t)r0 * NHQ + col]) = o0;
            *reinterpret_cast<float2*>(&outp[(size_t)r1 * NHQ + col]) = o1;
        }
    }
}

// ---------------- kernel 4: Ksum[b][d] = sum_a K[b,a,d] ----------------
__global__ void ksum_kernel() {
    int b  = blockIdx.x >> 2;
    int d  = (blockIdx.x & 3) * 256 + threadIdx.x;
    float s = 0.f;
#pragma unroll
    for (int a = 0; a < AA; a++)
        s += g_K[(size_t)(b * AA + a) * NHQ + d];
    g_ksum[b * NHQ + d] = s;
}

// ---------------- kernel 5: logits + softmax (one block per b, one warp per x) ----------------
__global__ void __launch_bounds__(1024, 1)
logits_softmax_kernel(const int* __restrict__ mask, float* __restrict__ out)
{
    int b = blockIdx.x;
    int wid = threadIdx.x >> 5, lid = threadIdx.x & 31;
    __shared__ float logits[AA];

    const float4* q  = reinterpret_cast<const float4*>(&g_Q[(size_t)(b * AA + wid) * NHQ]);
    const float4* k  = reinterpret_cast<const float4*>(&g_K[(size_t)(b * AA + wid) * NHQ]);
    const float4* ks = reinterpret_cast<const float4*>(&g_ksum[(size_t)b * NHQ]);
    float s = 0.f;
#pragma unroll
    for (int j = 0; j < 8; j++) {
        int idx = j * 32 + lid;
        float4 qv = q[idx], kv = k[idx], sv = ks[idx];
        s += qv.x * (sv.x - kv.x) + qv.y * (sv.y - kv.y)
           + qv.z * (sv.z - kv.z) + qv.w * (sv.w - kv.w);
    }
#pragma unroll
    for (int o = 16; o > 0; o >>= 1) s += __shfl_xor_sync(0xffffffffu, s, o);
    if (lid == 0) logits[wid] = s;
    __syncthreads();

    if (threadIdx.x < 32) {
        float m = (float)mask[b * AA + threadIdx.x];
        float l = logits[threadIdx.x] + (1.0f - m) * -100000.0f;
        float mx = l;
#pragma unroll
        for (int o = 16; o > 0; o >>= 1) mx = fmaxf(mx, __shfl_xor_sync(0xffffffffu, mx, o));
        float e = expf(l - mx);
        float se = e;
#pragma unroll
        for (int o = 16; o > 0; o >>= 1) se += __shfl_xor_sync(0xffffffffu, se, o);
        out[b * AA + threadIdx.x] = e / se;
    }
}

// ---------------- launch ----------------
extern "C" void kernel_launch(void* const* d_in, const int* in_sizes, int n_in,
                              void* d_out, int out_size)
{
    const float* enc  = (const float*)d_in[0];
    const int*   mask = (const int*)  d_in[1];
    const float* wq   = (const float*)d_in[2];
    const float* bq   = (const float*)d_in[3];
    const float* wk   = (const float*)d_in[4];
    const float* bk   = (const float*)d_in[5];
    float* out = (float*)d_out;

    static bool attr_set = false;
    if (!attr_set) {
        cudaFuncSetAttribute(gemm_mma_kernel, cudaFuncAttributeMaxDynamicSharedMemorySize, SMEM_TOTAL);
        attr_set = true;
    }

    split_cls_kernel<<<ROWS, 256>>>(enc);
    split_w_kernel<<<dim3(COLS2 / 32, DD / 32), 256>>>(wq, wk);
    gemm_mma_kernel<<<dim3(COLS2 / 128, ROWS / 128), 256, SMEM_TOTAL>>>(bq, bk, mask);
    ksum_kernel<<<BB * 4, 256>>>();
    logits_softmax_kernel<<<BB, 1024>>>(mask, out);
}

// round 6
// speedup vs baseline: 2.1815x; 1.4726x over previous
#include <cuda_runtime.h>
#include <cuda_fp16.h>
#include <cstdint>

// ---------------- problem shapes ----------------
#define BB 32
#define AA 32
#define SSQ 128
#define DD 1024
#define NHQ 1024                   // N*H
#define COLS2 2048                 // Q cols + K cols
#define ROWS 1024                  // B*A
#define ENC_ROW_STRIDE ((size_t)SSQ * DD)

#define LO_SCALE 256.0f
#define LO_INV   (1.0f / 256.0f)

// ---------------- device scratch (no allocs allowed) ----------------
__device__ __half g_A2[2][ROWS * DD];     // [hi/lo][row][k]   (CLS splits, lo *256)
__device__ __half g_B2[2][COLS2 * DD];    // [hi/lo][col][k]   (W^T splits, lo *256)
__device__ float g_Q[ROWS * NHQ];
__device__ float g_K[ROWS * NHQ];
__device__ float g_kpart[BB * 4 * NHQ];
__device__ float g_ksum[BB * NHQ];
__device__ float g_logits[BB * AA];

// ---------------- split helper ----------------
__device__ __forceinline__ void split2(float x, __half& h, __half& l) {
    h = __float2half_rn(x);
    float r = x - __half2float(h);
    l = __float2half_rn(r * LO_SCALE);
}

// ---------------- kernel 1: split CLS rows into 2 fp16 planes ----------------
__global__ void split_cls_kernel(const float* __restrict__ enc) {
    int r = blockIdx.x;
    int j = threadIdx.x;               // 256 threads, one float4 each (DD/4 = 256)
    float4 v = reinterpret_cast<const float4*>(enc + (size_t)r * ENC_ROW_STRIDE)[j];
    float xs[4] = {v.x, v.y, v.z, v.w};
    ushort4 ph, pl;
    unsigned short* hp = &ph.x; unsigned short* lp = &pl.x;
#pragma unroll
    for (int i = 0; i < 4; i++) {
        __half h, l;
        split2(xs[i], h, l);
        hp[i] = __half_as_ushort(h);
        lp[i] = __half_as_ushort(l);
    }
    size_t o = (size_t)r * DD + j * 4;
    *reinterpret_cast<ushort4*>(&g_A2[0][o]) = ph;
    *reinterpret_cast<ushort4*>(&g_A2[1][o]) = pl;
}

// ---------------- kernel 2: split + transpose W ([d][n] -> [col][k]) ----------------
__global__ void split_w_kernel(const float* __restrict__ wq, const float* __restrict__ wk) {
    __shared__ __half sh[2][32][33];
    int c0 = blockIdx.x * 32;          // global col tile (0..2047)
    int d0 = blockIdx.y * 32;
    int tx = threadIdx.x & 31;
    int ty = threadIdx.x >> 5;         // 0..7
    const float* W = (c0 < NHQ) ? wq : wk;
    int nb = (c0 < NHQ) ? c0 : (c0 - NHQ);
#pragma unroll
    for (int i = 0; i < 4; i++) {
        int dl = ty + i * 8;
        float x = W[(size_t)(d0 + dl) * NHQ + nb + tx];
        __half h, l;
        split2(x, h, l);
        sh[0][tx][dl] = h;             // [n_local][d_local]
        sh[1][tx][dl] = l;
    }
    __syncthreads();
#pragma unroll
    for (int i = 0; i < 4; i++) {
        int nl = ty + i * 8;
        size_t o = (size_t)(c0 + nl) * DD + d0 + tx;
        g_B2[0][o] = sh[0][nl][tx];
        g_B2[1][o] = sh[1][nl][tx];
    }
}

// ---------------- kernel 3: mma.sync fp16 GEMM, 2-split x 3 products ----------------
// CTA tile 128x128, K-chunk 64, 8 warps of 64x32 warp tiles, cp.async double buffer.
#define KC 64
#define NCHUNK (DD / KC)                     // 16
#define RSTR 72                              // smem row stride in halves (conflict-free)
#define PLANE_E (128 * RSTR)                 // 9216 halves per plane
#define STAGE_E (4 * PLANE_E)                // 36864 halves per stage
#define STAGE_B (STAGE_E * 2)                // 73728 bytes
#define SMEM_TOTAL (2 * STAGE_B)             // 147456 bytes

__device__ __forceinline__ uint32_t smem_u32(const void* p) {
    uint32_t a;
    asm("{ .reg .u64 t; cvta.to.shared.u64 t, %1; cvt.u32.u64 %0, t; }" : "=r"(a) : "l"(p));
    return a;
}
#define CP_ASYNC16(dst, src) \
    asm volatile("cp.async.cg.shared.global [%0], [%1], 16;" :: "r"(dst), "l"(src) : "memory")
#define CP_COMMIT() asm volatile("cp.async.commit_group;" ::: "memory")
#define CP_WAIT(N)  asm volatile("cp.async.wait_group %0;" :: "n"(N) : "memory")

__device__ __forceinline__ void mma_f16(float* c, const uint32_t* a, const uint32_t* b) {
    asm volatile(
        "mma.sync.aligned.m16n8k16.row.col.f32.f16.f16.f32 "
        "{%0,%1,%2,%3}, {%4,%5,%6,%7}, {%8,%9}, {%0,%1,%2,%3};"
        : "+f"(c[0]), "+f"(c[1]), "+f"(c[2]), "+f"(c[3])
        : "r"(a[0]), "r"(a[1]), "r"(a[2]), "r"(a[3]), "r"(b[0]), "r"(b[1]));
}

__device__ __forceinline__ void load_stage_async(uint32_t st_b, int tid, int tileR, int c0, int k0) {
#pragma unroll
    for (int it = 0; it < 16; it++) {
        int idx = tid + it * 256;            // 0..4095
        int t   = idx >> 10;                 // plane 0..3 (Ahi, Alo, Bhi, Blo)
        int e   = idx & 1023;
        int row = e >> 3;                    // 0..127
        int seg = e & 7;                     // 16B segment in the 128B row payload
        const __half* gsrc = (t < 2)
            ? &g_A2[t][(size_t)(tileR + row) * DD + k0 + seg * 8]
            : &g_B2[t - 2][(size_t)(c0 + row) * DD + k0 + seg * 8];
        uint32_t dst = st_b + (uint32_t)t * (PLANE_E * 2) + (uint32_t)row * (RSTR * 2) + seg * 16;
        CP_ASYNC16(dst, (const void*)__cvta_generic_to_global(gsrc));
    }
    CP_COMMIT();
}

__global__ void __launch_bounds__(256, 1)
gemm_mma_kernel(const float* __restrict__ bq, const float* __restrict__ bk,
                const int* __restrict__ mask)
{
    extern __shared__ __half smem[];          // 2 stages
    const uint32_t sb = smem_u32(smem);

    const int tid = threadIdx.x;
    const int wid = tid >> 5, lane = tid & 31;
    const int g = lane >> 2, t = lane & 3;    // mma group / thread-in-group
    const int wr = wid >> 2;                  // 0..1 -> m offset wr*64
    const int wc = wid & 3;                   // 0..3 -> n offset wc*32
    const int tileR = blockIdx.y * 128;
    const int c0 = blockIdx.x * 128;          // global col in [0,2048)

    float acc0[4][4][4];                      // hi*hi
    float acc1[4][4][4];                      // hi*lo + lo*hi  (x256 scale)
#pragma unroll
    for (int i = 0; i < 4; i++)
#pragma unroll
        for (int j = 0; j < 4; j++)
#pragma unroll
            for (int r = 0; r < 4; r++) { acc0[i][j][r] = 0.f; acc1[i][j][r] = 0.f; }

    load_stage_async(sb, tid, tileR, c0, 0);

    for (int c = 0; c < NCHUNK; c++) {
        if (c + 1 < NCHUNK) {
            load_stage_async(sb + (uint32_t)((c + 1) & 1) * STAGE_B, tid, tileR, c0, (c + 1) * KC);
            CP_WAIT(1);
        } else {
            CP_WAIT(0);
        }
        __syncthreads();

        const __half* s = smem + (size_t)(c & 1) * STAGE_E;
#pragma unroll
        for (int ks = 0; ks < 4; ks++) {
            uint32_t ah[4][4], al[4][4];
            uint32_t bh[4][2], bl[4][2];
#pragma unroll
            for (int mt = 0; mt < 4; mt++) {
                int rb = wr * 64 + mt * 16;
                const uint32_t* h0 = reinterpret_cast<const uint32_t*>(
                    s + 0 * PLANE_E + (rb + g) * RSTR + ks * 16 + t * 2);
                const uint32_t* h1 = reinterpret_cast<const uint32_t*>(
                    s + 0 * PLANE_E + (rb + g + 8) * RSTR + ks * 16 + t * 2);
                ah[mt][0] = h0[0]; ah[mt][1] = h1[0]; ah[mt][2] = h0[4]; ah[mt][3] = h1[4];
                const uint32_t* l0 = reinterpret_cast<const uint32_t*>(
                    s + 1 * PLANE_E + (rb + g) * RSTR + ks * 16 + t * 2);
                const uint32_t* l1 = reinterpret_cast<const uint32_t*>(
                    s + 1 * PLANE_E + (rb + g + 8) * RSTR + ks * 16 + t * 2);
                al[mt][0] = l0[0]; al[mt][1] = l1[0]; al[mt][2] = l0[4]; al[mt][3] = l1[4];
            }
#pragma unroll
            for (int nt = 0; nt < 4; nt++) {
                int rb = wc * 32 + nt * 8;
                const uint32_t* h0 = reinterpret_cast<const uint32_t*>(
                    s + 2 * PLANE_E + (rb + g) * RSTR + ks * 16 + t * 2);
                bh[nt][0] = h0[0]; bh[nt][1] = h0[4];
                const uint32_t* l0 = reinterpret_cast<const uint32_t*>(
                    s + 3 * PLANE_E + (rb + g) * RSTR + ks * 16 + t * 2);
                bl[nt][0] = l0[0]; bl[nt][1] = l0[4];
            }
#pragma unroll
            for (int mt = 0; mt < 4; mt++)
#pragma unroll
                for (int nt = 0; nt < 4; nt++) {
                    mma_f16(acc0[mt][nt], ah[mt], bh[nt]);
                    mma_f16(acc1[mt][nt], ah[mt], bl[nt]);
                    mma_f16(acc1[mt][nt], al[mt], bh[nt]);
                }
        }
        __syncthreads();
    }

    // ---------------- epilogue: combine splits, + bias, * mask, store ----------------
    const bool isK = (c0 >= NHQ);
    float* __restrict__ outp = isK ? g_K : g_Q;
    const float* __restrict__ bias = isK ? bk : bq;
    const int cb = isK ? (c0 - NHQ) : c0;

#pragma unroll
    for (int mt = 0; mt < 4; mt++) {
        int r0 = tileR + wr * 64 + mt * 16 + g;
        int r1 = r0 + 8;
        float m0 = (float)mask[r0];
        float m1 = (float)mask[r1];
#pragma unroll
        for (int nt = 0; nt < 4; nt++) {
            int col = cb + wc * 32 + nt * 8 + t * 2;
            float b0 = bias[col], b1 = bias[col + 1];
            float v0 = acc0[mt][nt][0] + acc1[mt][nt][0] * LO_INV;
            float v1 = acc0[mt][nt][1] + acc1[mt][nt][1] * LO_INV;
            float v2 = acc0[mt][nt][2] + acc1[mt][nt][2] * LO_INV;
            float v3 = acc0[mt][nt][3] + acc1[mt][nt][3] * LO_INV;
            float2 o0, o1;
            o0.x = (v0 + b0) * m0;
            o0.y = (v1 + b1) * m0;
            o1.x = (v2 + b0) * m1;
            o1.y = (v3 + b1) * m1;
            *reinterpret_cast<float2*>(&outp[(size_t)r0 * NHQ + col]) = o0;
            *reinterpret_cast<float2*>(&outp[(size_t)r1 * NHQ + col]) = o1;
        }
    }
}

// ---------------- kernel 4a: partial Ksum (512 blocks) ----------------
__global__ void ksum1_kernel() {
    int bx   = blockIdx.x;              // 0..511
    int b    = bx >> 4;
    int aseg = (bx >> 2) & 3;
    int dseg = bx & 3;
    int d    = dseg * 256 + threadIdx.x;
    float s = 0.f;
#pragma unroll
    for (int a = 0; a < 8; a++)
        s += g_K[(size_t)(b * AA + aseg * 8 + a) * NHQ + d];
    g_kpart[(size_t)(b * 4 + aseg) * NHQ + d] = s;
}

// ---------------- kernel 4b: final Ksum (128 blocks) ----------------
__global__ void ksum2_kernel() {
    int bx   = blockIdx.x;              // 0..127
    int b    = bx >> 2;
    int dseg = bx & 3;
    int d    = dseg * 256 + threadIdx.x;
    float s = 0.f;
#pragma unroll
    for (int i = 0; i < 4; i++)
        s += g_kpart[(size_t)(b * 4 + i) * NHQ + d];
    g_ksum[b * NHQ + d] = s;
}

// ---------------- kernel 5a: logits (128 blocks, one warp per x) ----------------
__global__ void __launch_bounds__(256, 1)
logits_kernel()
{
    int b = blockIdx.y;
    int x = blockIdx.x * 8 + (threadIdx.x >> 5);
    int lid = threadIdx.x & 31;

    const float4* q  = reinterpret_cast<const float4*>(&g_Q[(size_t)(b * AA + x) * NHQ]);
    const float4* k  = reinterpret_cast<const float4*>(&g_K[(size_t)(b * AA + x) * NHQ]);
    const float4* ks = reinterpret_cast<const float4*>(&g_ksum[(size_t)b * NHQ]);
    float s = 0.f;
#pragma unroll
    for (int j = 0; j < 8; j++) {
        int idx = j * 32 + lid;
        float4 qv = q[idx], kv = k[idx], sv = ks[idx];
        s += qv.x * (sv.x - kv.x) + qv.y * (sv.y - kv.y)
           + qv.z * (sv.z - kv.z) + qv.w * (sv.w - kv.w);
    }
#pragma unroll
    for (int o = 16; o > 0; o >>= 1) s += __shfl_xor_sync(0xffffffffu, s, o);
    if (lid == 0) g_logits[b * AA + x] = s;
}

// ---------------- kernel 5b: softmax (32 blocks x 32 threads) ----------------
__global__ void softmax_kernel(const int* __restrict__ mask, float* __restrict__ out)
{
    int b = blockIdx.x;
    int x = threadIdx.x;
    float m = (float)mask[b * AA + x];
    float l = g_logits[b * AA + x] + (1.0f - m) * -100000.0f;
    float mx = l;
#pragma unroll
    for (int o = 16; o > 0; o >>= 1) mx = fmaxf(mx, __shfl_xor_sync(0xffffffffu, mx, o));
    float e = expf(l - mx);
    float se = e;
#pragma unroll
    for (int o = 16; o > 0; o >>= 1) se += __shfl_xor_sync(0xffffffffu, se, o);
    out[b * AA + x] = e / se;
}

// ---------------- launch ----------------
extern "C" void kernel_launch(void* const* d_in, const int* in_sizes, int n_in,
                              void* d_out, int out_size)
{
    const float* enc  = (const float*)d_in[0];
    const int*   mask = (const int*)  d_in[1];
    const float* wq   = (const float*)d_in[2];
    const float* bq   = (const float*)d_in[3];
    const float* wk   = (const float*)d_in[4];
    const float* bk   = (const float*)d_in[5];
    float* out = (float*)d_out;

    static bool attr_set = false;
    if (!attr_set) {
        cudaFuncSetAttribute(gemm_mma_kernel, cudaFuncAttributeMaxDynamicSharedMemorySize, SMEM_TOTAL);
        attr_set = true;
    }

    split_cls_kernel<<<ROWS, 256>>>(enc);
    split_w_kernel<<<dim3(COLS2 / 32, DD / 32), 256>>>(wq, wk);
    gemm_mma_kernel<<<dim3(COLS2 / 128, ROWS / 128), 256, SMEM_TOTAL>>>(bq, bk, mask);
    ksum1_kernel<<<BB * 16, 256>>>();
    ksum2_kernel<<<BB * 4, 256>>>();
    logits_kernel<<<dim3(4, BB), 256>>>();
    softmax_kernel<<<BB, 32>>>(mask, out);
}

// round 8
// speedup vs baseline: 2.7715x; 1.2705x over previous
#include <cuda_runtime.h>
#include <cuda_fp16.h>
#include <cuda.h>
#include <cstdint>

// ---------------- problem shapes ----------------
#define BB 32
#define AA 32
#define SSQ 128
#define DD 1024
#define NHQ 1024                   // N*H
#define COLS2 2048                 // Q cols + K cols
#define ROWS 1024                  // B*A
#define ENC_ROW_STRIDE ((size_t)SSQ * DD)

#define LO_SCALE 256.0f
#define LO_INV   (1.0f / 256.0f)

// ---------------- device scratch (no allocs allowed) ----------------
__device__ __half g_A2[2][ROWS * DD];     // [hi/lo][row][k]   (CLS splits, lo *256)
__device__ __half g_B2[2][COLS2 * DD];    // [hi/lo][col][k]   (W^T splits, lo *256)
__device__ float g_Q[ROWS * NHQ];
__device__ float g_K[ROWS * NHQ];
__device__ float g_ksum[BB * NHQ];

// ---------------- split helper ----------------
__device__ __forceinline__ void split2(float x, __half& h, __half& l) {
    h = __float2half_rn(x);
    float r = x - __half2float(h);
    l = __float2half_rn(r * LO_SCALE);
}

// ---------------- kernel 1: split CLS rows into 2 fp16 planes ----------------
__global__ void split_cls_kernel(const float* __restrict__ enc) {
    int r = blockIdx.x;
    int j = threadIdx.x;               // 256 threads, one float4 each (DD/4 = 256)
    float4 v = reinterpret_cast<const float4*>(enc + (size_t)r * ENC_ROW_STRIDE)[j];
    float xs[4] = {v.x, v.y, v.z, v.w};
    ushort4 ph, pl;
    unsigned short* hp = &ph.x; unsigned short* lp = &pl.x;
#pragma unroll
    for (int i = 0; i < 4; i++) {
        __half h, l;
        split2(xs[i], h, l);
        hp[i] = __half_as_ushort(h);
        lp[i] = __half_as_ushort(l);
    }
    size_t o = (size_t)r * DD + j * 4;
    *reinterpret_cast<ushort4*>(&g_A2[0][o]) = ph;
    *reinterpret_cast<ushort4*>(&g_A2[1][o]) = pl;
}

// ---------------- kernel 2: split + transpose W ([d][n] -> [col][k]) ----------------
__global__ void split_w_kernel(const float* __restrict__ wq, const float* __restrict__ wk) {
    __shared__ __half sh[2][32][33];
    int c0 = blockIdx.x * 32;          // global col tile (0..2047)
    int d0 = blockIdx.y * 32;
    int tx = threadIdx.x & 31;
    int ty = threadIdx.x >> 5;         // 0..7
    const float* W = (c0 < NHQ) ? wq : wk;
    int nb = (c0 < NHQ) ? c0 : (c0 - NHQ);
#pragma unroll
    for (int i = 0; i < 4; i++) {
        int dl = ty + i * 8;
        float x = W[(size_t)(d0 + dl) * NHQ + nb + tx];
        __half h, l;
        split2(x, h, l);
        sh[0][tx][dl] = h;             // [n_local][d_local]
        sh[1][tx][dl] = l;
    }
    __syncthreads();
#pragma unroll
    for (int i = 0; i < 4; i++) {
        int nl = ty + i * 8;
        size_t o = (size_t)(c0 + nl) * DD + d0 + tx;
        g_B2[0][o] = sh[0][nl][tx];
        g_B2[1][o] = sh[1][nl][tx];
    }
}

// ---------------- GEMM: TMA + ldmatrix + mma.sync, 3-stage pipeline ----------------
#define KC 64
#define NCHUNK (DD / KC)                 // 16
#define TILE_BYTES 16384                 // one 128x128B plane tile
#define STAGE_BYTES (4 * TILE_BYTES)     // A-hi, A-lo, B-hi, B-lo = 64 KB
#define NSTAGE 3
#define SMEM_TILES 1024                  // barriers live below; stages 1024-aligned
#define SMEM_TOTAL (SMEM_TILES + NSTAGE * STAGE_BYTES)   // 197632

__device__ __forceinline__ uint32_t smem_u32(const void* p) {
    uint32_t a;
    asm("{ .reg .u64 t; cvta.to.shared.u64 t, %1; cvt.u32.u64 %0, t; }" : "=r"(a) : "l"(p));
    return a;
}
#define MBAR_INIT(mb, n)  asm volatile("mbarrier.init.shared.b64 [%0], %1;" :: "r"((uint32_t)(mb)), "r"((uint32_t)(n)) : "memory")
#define MBAR_EXPECT_TX(mb, bytes) asm volatile("mbarrier.arrive.expect_tx.shared.b64 _, [%0], %1;" :: "r"((uint32_t)(mb)), "r"((uint32_t)(bytes)) : "memory")
#define MBAR_WAIT(mb, ph) do {                                                          \
    uint32_t _mb = (uint32_t)(mb); uint32_t _p = (uint32_t)(ph); uint32_t _done;        \
    asm volatile("{\n\t.reg .pred p;\n\t"                                               \
        "mbarrier.try_wait.parity.acquire.cta.shared::cta.b64 p, [%1], %2;\n\t"         \
        "selp.b32 %0, 1, 0, p;\n\t}" : "=r"(_done) : "r"(_mb), "r"(_p) : "memory");     \
    if (!_done) {                                                                       \
        asm volatile("{\n\t.reg .pred P1;\n\t"                                          \
            "WL_%=:\n\t"                                                                \
            "mbarrier.try_wait.parity.acquire.cta.shared::cta.b64 P1, [%0], %1, 0x989680;\n\t" \
            "@P1 bra.uni WD_%=;\n\t"                                                    \
            "bra.uni WL_%=;\n\t"                                                        \
            "WD_%=:\n\t}" :: "r"(_mb), "r"(_p) : "memory");                             \
    }                                                                                   \
} while (0)

#define TMA_LOAD_3D(sm, mp, x, y, z, mb)                                                \
    asm volatile("cp.async.bulk.tensor.3d.shared::cta.global.tile.mbarrier::complete_tx::bytes " \
        "[%0], [%1, {%2, %3, %4}], [%5];"                                               \
        :: "r"((uint32_t)(sm)), "l"(mp), "r"((int)(x)), "r"((int)(y)), "r"((int)(z)),   \
           "r"((uint32_t)(mb)) : "memory")

#define LDMATRIX_X4(r0, r1, r2, r3, a)                                                  \
    asm volatile("ldmatrix.sync.aligned.m8n8.x4.shared.b16 {%0,%1,%2,%3}, [%4];"        \
        : "=r"(r0), "=r"(r1), "=r"(r2), "=r"(r3) : "r"(a))
#define LDMATRIX_X2(r0, r1, a)                                                          \
    asm volatile("ldmatrix.sync.aligned.m8n8.x2.shared.b16 {%0,%1}, [%2];"              \
        : "=r"(r0), "=r"(r1) : "r"(a))

__device__ __forceinline__ void mma_f16(float* c, const uint32_t* a, const uint32_t* b) {
    asm volatile(
        "mma.sync.aligned.m16n8k16.row.col.f32.f16.f16.f32 "
        "{%0,%1,%2,%3}, {%4,%5,%6,%7}, {%8,%9}, {%0,%1,%2,%3};"
        : "+f"(c[0]), "+f"(c[1]), "+f"(c[2]), "+f"(c[3])
        : "r"(a[0]), "r"(a[1]), "r"(a[2]), "r"(a[3]), "r"(b[0]), "r"(b[1]));
}

__global__ void __launch_bounds__(256, 1)
gemm_mma_kernel(const __grid_constant__ CUtensorMap tma_a,
                const __grid_constant__ CUtensorMap tma_b,
                const float* __restrict__ bq, const float* __restrict__ bk,
                const int* __restrict__ mask)
{
    extern __shared__ char smem[];
    const uint32_t sb = smem_u32(smem);

    const int tid = threadIdx.x;
    const int wid = tid >> 5, lane = tid & 31;
    const int g = lane >> 2, t = lane & 3;
    const int wr = wid >> 2;                  // 0..1 -> m offset wr*64
    const int wc = wid & 3;                   // 0..3 -> n offset wc*32
    const int tileR = blockIdx.y * 128;
    const int c0 = blockIdx.x * 128;          // global col in [0,2048)

    // mbarrier init + prologue TMA (stages 0..2)
    if (tid == 0) {
#pragma unroll
        for (int s = 0; s < NSTAGE; s++) MBAR_INIT(sb + s * 8, 1);
    }
    __syncthreads();
    if (tid == 0) {
#pragma unroll
        for (int s = 0; s < NSTAGE; s++) {
            uint32_t stg = sb + SMEM_TILES + s * STAGE_BYTES;
            MBAR_EXPECT_TX(sb + s * 8, STAGE_BYTES);
#pragma unroll
            for (int p = 0; p < 2; p++) {
                TMA_LOAD_3D(stg + p * TILE_BYTES,       &tma_a, s * KC, tileR, p, sb + s * 8);
                TMA_LOAD_3D(stg + (2 + p) * TILE_BYTES, &tma_b, s * KC, c0,    p, sb + s * 8);
            }
        }
    }

    // per-lane ldmatrix address components (swizzle xor depends only on lane&7)
    const int xr = (lane & 7) << 4;                        // SW128 xor term
    const int a_row_local = (lane & 7) + ((lane >> 3) & 1) * 8;
    const int a_kh16 = ((lane >> 4) & 1) * 16;
    const int b_row_local = lane & 7;
    const int b_kh16 = ((lane >> 3) & 1) * 16;

    uint32_t aro[4], bro[4];
#pragma unroll
    for (int mt = 0; mt < 4; mt++) aro[mt] = (uint32_t)(wr * 64 + mt * 16 + a_row_local) * 128;
#pragma unroll
    for (int nt = 0; nt < 4; nt++) bro[nt] = (uint32_t)(wc * 32 + nt * 8 + b_row_local) * 128;

    float acc0[4][4][4];                      // hi*hi
    float acc1[4][4][4];                      // hi*lo + lo*hi (x256 scale)
#pragma unroll
    for (int i = 0; i < 4; i++)
#pragma unroll
        for (int j = 0; j < 4; j++)
#pragma unroll
            for (int r = 0; r < 4; r++) { acc0[i][j][r] = 0.f; acc1[i][j][r] = 0.f; }

    for (int c = 0; c < NCHUNK; c++) {
        const int s = c % NSTAGE;
        MBAR_WAIT(sb + s * 8, (c / NSTAGE) & 1);
        const uint32_t stg = sb + SMEM_TILES + (uint32_t)s * STAGE_BYTES;

#pragma unroll
        for (int ks = 0; ks < 4; ks++) {
            const uint32_t akt = (uint32_t)((ks * 32 + a_kh16) ^ xr);
            const uint32_t bkt = (uint32_t)((ks * 32 + b_kh16) ^ xr);
            uint32_t ah[4][4], al[4][4];
            uint32_t bh[4][2], bl[4][2];
#pragma unroll
            for (int mt = 0; mt < 4; mt++) {
                LDMATRIX_X4(ah[mt][0], ah[mt][1], ah[mt][2], ah[mt][3],
                            stg + 0 * TILE_BYTES + aro[mt] + akt);
                LDMATRIX_X4(al[mt][0], al[mt][1], al[mt][2], al[mt][3],
                            stg + 1 * TILE_BYTES + aro[mt] + akt);
            }
#pragma unroll
            for (int nt = 0; nt < 4; nt++) {
                LDMATRIX_X2(bh[nt][0], bh[nt][1], stg + 2 * TILE_BYTES + bro[nt] + bkt);
                LDMATRIX_X2(bl[nt][0], bl[nt][1], stg + 3 * TILE_BYTES + bro[nt] + bkt);
            }
#pragma unroll
            for (int mt = 0; mt < 4; mt++)
#pragma unroll
                for (int nt = 0; nt < 4; nt++) {
                    mma_f16(acc0[mt][nt], ah[mt], bh[nt]);
                    mma_f16(acc1[mt][nt], ah[mt], bl[nt]);
                    mma_f16(acc1[mt][nt], al[mt], bh[nt]);
                }
        }
        __syncthreads();                       // everyone done with stage s
        if (c + NSTAGE < NCHUNK && tid == 0) {
            uint32_t dst = sb + SMEM_TILES + (uint32_t)s * STAGE_BYTES;
            MBAR_EXPECT_TX(sb + s * 8, STAGE_BYTES);
            int k0 = (c + NSTAGE) * KC;
#pragma unroll
            for (int p = 0; p < 2; p++) {
                TMA_LOAD_3D(dst + p * TILE_BYTES,       &tma_a, k0, tileR, p, sb + s * 8);
                TMA_LOAD_3D(dst + (2 + p) * TILE_BYTES, &tma_b, k0, c0,    p, sb + s * 8);
            }
        }
    }

    // ---------------- epilogue: combine splits, + bias, * mask, store ----------------
    const bool isK = (c0 >= NHQ);
    float* __restrict__ outp = isK ? g_K : g_Q;
    const float* __restrict__ bias = isK ? bk : bq;
    const int cb = isK ? (c0 - NHQ) : c0;

#pragma unroll
    for (int mt = 0; mt < 4; mt++) {
        int r0 = tileR + wr * 64 + mt * 16 + g;
        int r1 = r0 + 8;
        float m0 = (float)mask[r0];
        float m1 = (float)mask[r1];
#pragma unroll
        for (int nt = 0; nt < 4; nt++) {
            int col = cb + wc * 32 + nt * 8 + t * 2;
            float b0 = bias[col], b1 = bias[col + 1];
            float v0 = acc0[mt][nt][0] + acc1[mt][nt][0] * LO_INV;
            float v1 = acc0[mt][nt][1] + acc1[mt][nt][1] * LO_INV;
            float v2 = acc0[mt][nt][2] + acc1[mt][nt][2] * LO_INV;
            float v3 = acc0[mt][nt][3] + acc1[mt][nt][3] * LO_INV;
            float2 o0, o1;
            o0.x = (v0 + b0) * m0;
            o0.y = (v1 + b1) * m0;
            o1.x = (v2 + b0) * m1;
            o1.y = (v3 + b1) * m1;
            *reinterpret_cast<float2*>(&outp[(size_t)r0 * NHQ + col]) = o0;
            *reinterpret_cast<float2*>(&outp[(size_t)r1 * NHQ + col]) = o1;
        }
    }
}

// ---------------- kernel 4: Ksum (single kernel, 128 blocks) ----------------
__global__ void __launch_bounds__(256, 1) ksum_kernel() {
    __shared__ float4 red[4][64];
    int b    = blockIdx.x >> 2;
    int dseg = blockIdx.x & 3;
    int f4   = threadIdx.x & 63;
    int ag   = threadIdx.x >> 6;          // 0..3, each sums 8 'a' rows
    const float4* base = reinterpret_cast<const float4*>(
        &g_K[(size_t)(b * AA + ag * 8) * NHQ + dseg * 256]) + f4;
    float4 s = {0.f, 0.f, 0.f, 0.f};
#pragma unroll
    for (int a = 0; a < 8; a++) {
        float4 v = base[(size_t)a * (NHQ / 4)];
        s.x += v.x; s.y += v.y; s.z += v.z; s.w += v.w;
    }
    red[ag][f4] = s;
    __syncthreads();
    if (ag == 0) {
        float4 t0 = red[0][f4], t1 = red[1][f4], t2 = red[2][f4], t3 = red[3][f4];
        float4 o;
        o.x = t0.x + t1.x + t2.x + t3.x;
        o.y = t0.y + t1.y + t2.y + t3.y;
        o.z = t0.z + t1.z + t2.z + t3.z;
        o.w = t0.w + t1.w + t2.w + t3.w;
        reinterpret_cast<float4*>(&g_ksum[(size_t)b * NHQ + dseg * 256])[f4] = o;
    }
}

// ---------------- kernel 5: logits + softmax (32 blocks x 1024 threads) ----------------
__global__ void __launch_bounds__(1024, 1)
logits_softmax_kernel(const int* __restrict__ mask, float* __restrict__ out)
{
    int b = blockIdx.x;
    int wid = threadIdx.x >> 5, lid = threadIdx.x & 31;
    __shared__ float logits[AA];

    const float4* q  = reinterpret_cast<const float4*>(&g_Q[(size_t)(b * AA + wid) * NHQ]);
    const float4* k  = reinterpret_cast<const float4*>(&g_K[(size_t)(b * AA + wid) * NHQ]);
    const float4* ks = reinterpret_cast<const float4*>(&g_ksum[(size_t)b * NHQ]);
    float s = 0.f;
#pragma unroll
    for (int j = 0; j < 8; j++) {
        int idx = j * 32 + lid;
        float4 qv = q[idx], kv = k[idx], sv = ks[idx];
        s += qv.x * (sv.x - kv.x) + qv.y * (sv.y - kv.y)
           + qv.z * (sv.z - kv.z) + qv.w * (sv.w - kv.w);
    }
#pragma unroll
    for (int o = 16; o > 0; o >>= 1) s += __shfl_xor_sync(0xffffffffu, s, o);
    if (lid == 0) logits[wid] = s;
    __syncthreads();

    if (threadIdx.x < 32) {
        float m = (float)mask[b * AA + threadIdx.x];
        float l = logits[threadIdx.x] + (1.0f - m) * -100000.0f;
        float mx = l;
#pragma unroll
        for (int o = 16; o > 0; o >>= 1) mx = fmaxf(mx, __shfl_xor_sync(0xffffffffu, mx, o));
        float e = expf(l - mx);
        float se = e;
#pragma unroll
        for (int o = 16; o > 0; o >>= 1) se += __shfl_xor_sync(0xffffffffu, se, o);
        out[b * AA + threadIdx.x] = e / se;
    }
}

// ---------------- host: tensor map construction ----------------
typedef CUresult (*EncodeTiledFn)(
    CUtensorMap*, CUtensorMapDataType, cuuint32_t, void*,
    const cuuint64_t*, const cuuint64_t*, const cuuint32_t*, const cuuint32_t*,
    CUtensorMapInterleave, CUtensorMapSwizzle, CUtensorMapL2promotion, CUtensorMapFloatOOBfill);

extern "C" void kernel_launch(void* const* d_in, const int* in_sizes, int n_in,
                              void* d_out, int out_size)
{
    const float* enc  = (const float*)d_in[0];
    const int*   mask = (const int*)  d_in[1];
    const float* wq   = (const float*)d_in[2];
    const float* bq   = (const float*)d_in[3];
    const float* wk   = (const float*)d_in[4];
    const float* bk   = (const float*)d_in[5];
    float* out = (float*)d_out;

    cudaFuncSetAttribute(gemm_mma_kernel, cudaFuncAttributeMaxDynamicSharedMemorySize, SMEM_TOTAL);

    // Build tensor maps (host-side, deterministic, capture-legal)
    void* fn = nullptr;
    cudaDriverEntryPointQueryResult qr;
    cudaGetDriverEntryPointByVersion("cuTensorMapEncodeTiled", &fn, 12000,
                                     cudaEnableDefault, &qr);
    EncodeTiledFn encode = (EncodeTiledFn)fn;

    void *pA = nullptr, *pB = nullptr;
    cudaGetSymbolAddress(&pA, g_A2);
    cudaGetSymbolAddress(&pB, g_B2);

    CUtensorMap tmaA, tmaB;
    {
        cuuint64_t dims[3]    = {DD, ROWS, 2};
        cuuint64_t strides[2] = {DD * 2ull, (cuuint64_t)ROWS * DD * 2ull};
        cuuint32_t box[3]     = {KC, 128, 1};
        cuuint32_t es[3]      = {1, 1, 1};
        encode(&tmaA, CU_TENSOR_MAP_DATA_TYPE_UINT16, 3, pA, dims, strides, box, es,
               CU_TENSOR_MAP_INTERLEAVE_NONE, CU_TENSOR_MAP_SWIZZLE_128B,
               CU_TENSOR_MAP_L2_PROMOTION_L2_128B, CU_TENSOR_MAP_FLOAT_OOB_FILL_NONE);
    }
    {
        cuuint64_t dims[3]    = {DD, COLS2, 2};
        cuuint64_t strides[2] = {DD * 2ull, (cuuint64_t)COLS2 * DD * 2ull};
        cuuint32_t box[3]     = {KC, 128, 1};
        cuuint32_t es[3]      = {1, 1, 1};
        encode(&tmaB, CU_TENSOR_MAP_DATA_TYPE_UINT16, 3, pB, dims, strides, box, es,
               CU_TENSOR_MAP_INTERLEAVE_NONE, CU_TENSOR_MAP_SWIZZLE_128B,
               CU_TENSOR_MAP_L2_PROMOTION_L2_128B, CU_TENSOR_MAP_FLOAT_OOB_FILL_NONE);
    }

    split_cls_kernel<<<ROWS, 256>>>(enc);
    split_w_kernel<<<dim3(COLS2 / 32, DD / 32), 256>>>(wq, wk);
    gemm_mma_kernel<<<dim3(COLS2 / 128, ROWS / 128), 256, SMEM_TOTAL>>>(tmaA, tmaB, bq, bk, mask);
    ksum_kernel<<<BB * 4, 256>>>();
    logits_softmax_kernel<<<BB, 1024>>>(mask, out);
}

// round 10
// speedup vs baseline: 2.8948x; 1.0445x over previous
#include <cuda_runtime.h>
#include <cuda_fp16.h>
#include <cuda.h>
#include <cstdint>

// ---------------- problem shapes ----------------
#define BB 32
#define AA 32
#define SSQ 128
#define DD 1024
#define NHQ 1024                   // N*H
#define COLS2 2048                 // Q cols + K cols
#define ROWS 1024                  // B*A
#define ENC_ROW_STRIDE ((size_t)SSQ * DD)

#define LO_SCALE 256.0f
#define LO_INV   (1.0f / 256.0f)

// ---------------- device scratch (no allocs allowed) ----------------
__device__ __half g_A2[2][ROWS * DD];     // [hi/lo][row][k]   (CLS splits, lo *256)
__device__ __half g_B2[2][COLS2 * DD];    // [hi/lo][col][k]   (W^T splits, lo *256)
__device__ float g_Q[ROWS * NHQ];
__device__ float g_K[ROWS * NHQ];
__device__ float g_ksum[BB * NHQ];

// ---------------- split helper ----------------
__device__ __forceinline__ void split2(float x, __half& h, __half& l) {
    h = __float2half_rn(x);
    float r = x - __half2float(h);
    l = __float2half_rn(r * LO_SCALE);
}

// ---------------- kernel 1: fused splits (CLS + W) ----------------
__global__ void __launch_bounds__(256, 1)
split_all_kernel(const float* __restrict__ enc,
                 const float* __restrict__ wq, const float* __restrict__ wk)
{
    int bx = blockIdx.x;
    if (bx < ROWS) {
        // ---- CLS rows -> 2 fp16 planes ----
        int r = bx;
        int j = threadIdx.x;               // one float4 each (DD/4 = 256)
        float4 v = reinterpret_cast<const float4*>(enc + (size_t)r * ENC_ROW_STRIDE)[j];
        float xs[4] = {v.x, v.y, v.z, v.w};
        ushort4 ph, pl;
        unsigned short* hp = &ph.x; unsigned short* lp = &pl.x;
#pragma unroll
        for (int i = 0; i < 4; i++) {
            __half h, l;
            split2(xs[i], h, l);
            hp[i] = __half_as_ushort(h);
            lp[i] = __half_as_ushort(l);
        }
        size_t o = (size_t)r * DD + j * 4;
        *reinterpret_cast<ushort4*>(&g_A2[0][o]) = ph;
        *reinterpret_cast<ushort4*>(&g_A2[1][o]) = pl;
    } else {
        // ---- W split + transpose ([d][n] -> [col][k]) ----
        __shared__ __half sh[2][32][33];
        int idx = bx - ROWS;               // 0..2047
        int c0 = (idx & 63) * 32;          // global col tile (0..2047)
        int d0 = (idx >> 6) * 32;
        int tx = threadIdx.x & 31;
        int ty = threadIdx.x >> 5;         // 0..7
        const float* W = (c0 < NHQ) ? wq : wk;
        int nb = (c0 < NHQ) ? c0 : (c0 - NHQ);
#pragma unroll
        for (int i = 0; i < 4; i++) {
            int dl = ty + i * 8;
            float x = W[(size_t)(d0 + dl) * NHQ + nb + tx];
            __half h, l;
            split2(x, h, l);
            sh[0][tx][dl] = h;             // [n_local][d_local]
            sh[1][tx][dl] = l;
        }
        __syncthreads();
#pragma unroll
        for (int i = 0; i < 4; i++) {
            int nl = ty + i * 8;
            size_t o = (size_t)(c0 + nl) * DD + d0 + tx;
            g_B2[0][o] = sh[0][nl][tx];
            g_B2[1][o] = sh[1][nl][tx];
        }
    }
}

// ---------------- GEMM: TMA + ldmatrix + mma.sync, 3-stage pipeline ----------------
#define KC 64
#define NCHUNK (DD / KC)                 // 16
#define TILE_BYTES 16384                 // one 128x128B plane tile
#define STAGE_BYTES (4 * TILE_BYTES)     // A-hi, A-lo, B-hi, B-lo = 64 KB
#define NSTAGE 3
#define SMEM_TILES 1024                  // barriers live below; stages 1024-aligned
#define SMEM_TOTAL (SMEM_TILES + NSTAGE * STAGE_BYTES)   // 197632

__device__ __forceinline__ uint32_t smem_u32(const void* p) {
    uint32_t a;
    asm("{ .reg .u64 t; cvta.to.shared.u64 t, %1; cvt.u32.u64 %0, t; }" : "=r"(a) : "l"(p));
    return a;
}
#define MBAR_INIT(mb, n)  asm volatile("mbarrier.init.shared.b64 [%0], %1;" :: "r"((uint32_t)(mb)), "r"((uint32_t)(n)) : "memory")
#define MBAR_EXPECT_TX(mb, bytes) asm volatile("mbarrier.arrive.expect_tx.shared.b64 _, [%0], %1;" :: "r"((uint32_t)(mb)), "r"((uint32_t)(bytes)) : "memory")
#define MBAR_WAIT(mb, ph) do {                                                          \
    uint32_t _mb = (uint32_t)(mb); uint32_t _p = (uint32_t)(ph); uint32_t _done;        \
    asm volatile("{\n\t.reg .pred p;\n\t"                                               \
        "mbarrier.try_wait.parity.acquire.cta.shared::cta.b64 p, [%1], %2;\n\t"         \
        "selp.b32 %0, 1, 0, p;\n\t}" : "=r"(_done) : "r"(_mb), "r"(_p) : "memory");     \
    if (!_done) {                                                                       \
        asm volatile("{\n\t.reg .pred P1;\n\t"                                          \
            "WL_%=:\n\t"                                                                \
            "mbarrier.try_wait.parity.acquire.cta.shared::cta.b64 P1, [%0], %1, 0x989680;\n\t" \
            "@P1 bra.uni WD_%=;\n\t"                                                    \
            "bra.uni WL_%=;\n\t"                                                        \
            "WD_%=:\n\t}" :: "r"(_mb), "r"(_p) : "memory");                             \
    }                                                                                   \
} while (0)

#define TMA_LOAD_3D(sm, mp, x, y, z, mb)                                                \
    asm volatile("cp.async.bulk.tensor.3d.shared::cta.global.tile.mbarrier::complete_tx::bytes " \
        "[%0], [%1, {%2, %3, %4}], [%5];"                                               \
        :: "r"((uint32_t)(sm)), "l"(mp), "r"((int)(x)), "r"((int)(y)), "r"((int)(z)),   \
           "r"((uint32_t)(mb)) : "memory")

#define LDMATRIX_X4(r0, r1, r2, r3, a)                                                  \
    asm volatile("ldmatrix.sync.aligned.m8n8.x4.shared.b16 {%0,%1,%2,%3}, [%4];"        \
        : "=r"(r0), "=r"(r1), "=r"(r2), "=r"(r3) : "r"(a))
#define LDMATRIX_X2(r0, r1, a)                                                          \
    asm volatile("ldmatrix.sync.aligned.m8n8.x2.shared.b16 {%0,%1}, [%2];"              \
        : "=r"(r0), "=r"(r1) : "r"(a))

__device__ __forceinline__ void mma_f16(float* c, const uint32_t* a, const uint32_t* b) {
    asm volatile(
        "mma.sync.aligned.m16n8k16.row.col.f32.f16.f16.f32 "
        "{%0,%1,%2,%3}, {%4,%5,%6,%7}, {%8,%9}, {%0,%1,%2,%3};"
        : "+f"(c[0]), "+f"(c[1]), "+f"(c[2]), "+f"(c[3])
        : "r"(a[0]), "r"(a[1]), "r"(a[2]), "r"(a[3]), "r"(b[0]), "r"(b[1]));
}

__global__ void __launch_bounds__(256, 1)
gemm_mma_kernel(const __grid_constant__ CUtensorMap tma_a,
                const __grid_constant__ CUtensorMap tma_b,
                const float* __restrict__ bq, const float* __restrict__ bk,
                const int* __restrict__ mask)
{
    extern __shared__ char smem[];
    const uint32_t sb = smem_u32(smem);

    const int tid = threadIdx.x;
    const int wid = tid >> 5, lane = tid & 31;
    const int g = lane >> 2, t = lane & 3;
    const int wr = wid >> 2;                  // 0..1 -> m offset wr*64
    const int wc = wid & 3;                   // 0..3 -> n offset wc*32
    const int tileR = blockIdx.y * 128;
    const int c0 = blockIdx.x * 128;          // global col in [0,2048)

    // mbarrier init + prologue TMA (stages 0..2)
    if (tid == 0) {
#pragma unroll
        for (int s = 0; s < NSTAGE; s++) MBAR_INIT(sb + s * 8, 1);
    }
    __syncthreads();
    if (tid == 0) {
#pragma unroll
        for (int s = 0; s < NSTAGE; s++) {
            uint32_t stg = sb + SMEM_TILES + s * STAGE_BYTES;
            MBAR_EXPECT_TX(sb + s * 8, STAGE_BYTES);
#pragma unroll
            for (int p = 0; p < 2; p++) {
                TMA_LOAD_3D(stg + p * TILE_BYTES,       &tma_a, s * KC, tileR, p, sb + s * 8);
                TMA_LOAD_3D(stg + (2 + p) * TILE_BYTES, &tma_b, s * KC, c0,    p, sb + s * 8);
            }
        }
    }

    // per-lane ldmatrix address components (swizzle xor depends only on lane&7)
    const int xr = (lane & 7) << 4;                        // SW128 xor term
    const int a_row_local = (lane & 7) + ((lane >> 3) & 1) * 8;
    const int a_kh16 = ((lane >> 4) & 1) * 16;
    const int b_row_local = lane & 7;
    const int b_kh16 = ((lane >> 3) & 1) * 16;

    uint32_t aro[4], bro[4];
#pragma unroll
    for (int mt = 0; mt < 4; mt++) aro[mt] = (uint32_t)(wr * 64 + mt * 16 + a_row_local) * 128;
#pragma unroll
    for (int nt = 0; nt < 4; nt++) bro[nt] = (uint32_t)(wc * 32 + nt * 8 + b_row_local) * 128;

    float acc0[4][4][4];                      // hi*hi
    float acc1[4][4][4];                      // hi*lo + lo*hi (x256 scale)
#pragma unroll
    for (int i = 0; i < 4; i++)
#pragma unroll
        for (int j = 0; j < 4; j++)
#pragma unroll
            for (int r = 0; r < 4; r++) { acc0[i][j][r] = 0.f; acc1[i][j][r] = 0.f; }

    for (int c = 0; c < NCHUNK; c++) {
        const int s = c % NSTAGE;
        MBAR_WAIT(sb + s * 8, (c / NSTAGE) & 1);
        const uint32_t stg = sb + SMEM_TILES + (uint32_t)s * STAGE_BYTES;

#pragma unroll
        for (int ks = 0; ks < 4; ks++) {
            const uint32_t akt = (uint32_t)((ks * 32 + a_kh16) ^ xr);
            const uint32_t bkt = (uint32_t)((ks * 32 + b_kh16) ^ xr);
            uint32_t ah[4][4], al[4][4];
            uint32_t bh[4][2], bl[4][2];
#pragma unroll
            for (int mt = 0; mt < 4; mt++) {
                LDMATRIX_X4(ah[mt][0], ah[mt][1], ah[mt][2], ah[mt][3],
                            stg + 0 * TILE_BYTES + aro[mt] + akt);
                LDMATRIX_X4(al[mt][0], al[mt][1], al[mt][2], al[mt][3],
                            stg + 1 * TILE_BYTES + aro[mt] + akt);
            }
#pragma unroll
            for (int nt = 0; nt < 4; nt++) {
                LDMATRIX_X2(bh[nt][0], bh[nt][1], stg + 2 * TILE_BYTES + bro[nt] + bkt);
                LDMATRIX_X2(bl[nt][0], bl[nt][1], stg + 3 * TILE_BYTES + bro[nt] + bkt);
            }
#pragma unroll
            for (int mt = 0; mt < 4; mt++)
#pragma unroll
                for (int nt = 0; nt < 4; nt++) {
                    mma_f16(acc0[mt][nt], ah[mt], bh[nt]);
                    mma_f16(acc1[mt][nt], ah[mt], bl[nt]);
                    mma_f16(acc1[mt][nt], al[mt], bh[nt]);
                }
        }
        __syncthreads();                       // everyone done with stage s
        if (c + NSTAGE < NCHUNK && tid == 0) {
            uint32_t dst = sb + SMEM_TILES + (uint32_t)s * STAGE_BYTES;
            MBAR_EXPECT_TX(sb + s * 8, STAGE_BYTES);
            int k0 = (c + NSTAGE) * KC;
#pragma unroll
            for (int p = 0; p < 2; p++) {
                TMA_LOAD_3D(dst + p * TILE_BYTES,       &tma_a, k0, tileR, p, sb + s * 8);
                TMA_LOAD_3D(dst + (2 + p) * TILE_BYTES, &tma_b, k0, c0,    p, sb + s * 8);
            }
        }
    }

    // ---------------- epilogue: combine splits, + bias, * mask, store, fused ksum ----------------
    const bool isK = (c0 >= NHQ);
    float* __restrict__ outp = isK ? g_K : g_Q;
    const float* __restrict__ bias = isK ? bk : bq;
    const int cb = isK ? (c0 - NHQ) : c0;

    float ksacc[2][4][2];                     // [batch-local p][nt][col pair]
#pragma unroll
    for (int p = 0; p < 2; p++)
#pragma unroll
        for (int nt = 0; nt < 4; nt++) { ksacc[p][nt][0] = 0.f; ksacc[p][nt][1] = 0.f; }

#pragma unroll
    for (int mt = 0; mt < 4; mt++) {
        int r0 = tileR + wr * 64 + mt * 16 + g;
        int r1 = r0 + 8;
        float m0 = (float)mask[r0];
        float m1 = (float)mask[r1];
#pragma unroll
        for (int nt = 0; nt < 4; nt++) {
            int col = cb + wc * 32 + nt * 8 + t * 2;
            float b0 = bias[col], b1 = bias[col + 1];
            float v0 = acc0[mt][nt][0] + acc1[mt][nt][0] * LO_INV;
            float v1 = acc0[mt][nt][1] + acc1[mt][nt][1] * LO_INV;
            float v2 = acc0[mt][nt][2] + acc1[mt][nt][2] * LO_INV;
            float v3 = acc0[mt][nt][3] + acc1[mt][nt][3] * LO_INV;
            float2 o0, o1;
            o0.x = (v0 + b0) * m0;
            o0.y = (v1 + b1) * m0;
            o1.x = (v2 + b0) * m1;
            o1.y = (v3 + b1) * m1;
            *reinterpret_cast<float2*>(&outp[(size_t)r0 * NHQ + col]) = o0;
            *reinterpret_cast<float2*>(&outp[(size_t)r1 * NHQ + col]) = o1;
            if (isK) {
                int p = mt >> 1;               // batch-local index within warp (32-row groups)
                ksacc[p][nt][0] += o0.x + o1.x;
                ksacc[p][nt][1] += o0.y + o1.y;
            }
        }
    }

    if (isK) {
        // reduce over the g lanes (rows within the 32-row batch held by this warp)
#pragma unroll
        for (int p = 0; p < 2; p++)
#pragma unroll
            for (int nt = 0; nt < 4; nt++)
#pragma unroll
                for (int c2 = 0; c2 < 2; c2++) {
                    float v = ksacc[p][nt][c2];
                    v += __shfl_xor_sync(0xffffffffu, v, 4);
                    v += __shfl_xor_sync(0xffffffffu, v, 8);
                    v += __shfl_xor_sync(0xffffffffu, v, 16);
                    ksacc[p][nt][c2] = v;
                }
        if (g == 0) {                          // lanes 0..3 hold final sums
#pragma unroll
            for (int p = 0; p < 2; p++) {
                int batch = blockIdx.y * 4 + wr * 2 + p;
#pragma unroll
                for (int nt = 0; nt < 4; nt++) {
                    int col = cb + wc * 32 + nt * 8 + t * 2;
                    float2 o = {ksacc[p][nt][0], ksacc[p][nt][1]};
                    *reinterpret_cast<float2*>(&g_ksum[(size_t)batch * NHQ + col]) = o;
                }
            }
        }
    }
}

// ---------------- kernel 3: logits + softmax (32 blocks x 1024 threads) ----------------
__global__ void __launch_bounds__(1024, 1)
logits_softmax_kernel(const int* __restrict__ mask, float* __restrict__ out)
{
    int b = blockIdx.x;
    int wid = threadIdx.x >> 5, lid = threadIdx.x & 31;
    __shared__ float logits[AA];

    const float4* q  = reinterpret_cast<const float4*>(&g_Q[(size_t)(b * AA + wid) * NHQ]);
    const float4* k  = reinterpret_cast<const float4*>(&g_K[(size_t)(b * AA + wid) * NHQ]);
    const float4* ks = reinterpret_cast<const float4*>(&g_ksum[(size_t)b * NHQ]);
    float s = 0.f;
#pragma unroll
    for (int j = 0; j < 8; j++) {
        int idx = j * 32 + lid;
        float4 qv = q[idx], kv = k[idx], sv = ks[idx];
        s += qv.x * (sv.x - kv.x) + qv.y * (sv.y - kv.y)
           + qv.z * (sv.z - kv.z) + qv.w * (sv.w - kv.w);
    }
#pragma unroll
    for (int o = 16; o > 0; o >>= 1) s += __shfl_xor_sync(0xffffffffu, s, o);
    if (lid == 0) logits[wid] = s;
    __syncthreads();

    if (threadIdx.x < 32) {
        float m = (float)mask[b * AA + threadIdx.x];
        float l = logits[threadIdx.x] + (1.0f - m) * -100000.0f;
        float mx = l;
#pragma unroll
        for (int o = 16; o > 0; o >>= 1) mx = fmaxf(mx, __shfl_xor_sync(0xffffffffu, mx, o));
        float e = expf(l - mx);
        float se = e;
#pragma unroll
        for (int o = 16; o > 0; o >>= 1) se += __shfl_xor_sync(0xffffffffu, se, o);
        out[b * AA + threadIdx.x] = e / se;
    }
}

// ---------------- host: tensor map construction ----------------
typedef CUresult (*EncodeTiledFn)(
    CUtensorMap*, CUtensorMapDataType, cuuint32_t, void*,
    const cuuint64_t*, const cuuint64_t*, const cuuint32_t*, const cuuint32_t*,
    CUtensorMapInterleave, CUtensorMapSwizzle, CUtensorMapL2promotion, CUtensorMapFloatOOBfill);

extern "C" void kernel_launch(void* const* d_in, const int* in_sizes, int n_in,
                              void* d_out, int out_size)
{
    const float* enc  = (const float*)d_in[0];
    const int*   mask = (const int*)  d_in[1];
    const float* wq   = (const float*)d_in[2];
    const float* bq   = (const float*)d_in[3];
    const float* wk   = (const float*)d_in[4];
    const float* bk   = (const float*)d_in[5];
    float* out = (float*)d_out;

    cudaFuncSetAttribute(gemm_mma_kernel, cudaFuncAttributeMaxDynamicSharedMemorySize, SMEM_TOTAL);

    // Build tensor maps (host-side, deterministic, capture-legal)
    void* fn = nullptr;
    cudaDriverEntryPointQueryResult qr;
    cudaGetDriverEntryPointByVersion("cuTensorMapEncodeTiled", &fn, 12000,
                                     cudaEnableDefault, &qr);
    EncodeTiledFn encode = (EncodeTiledFn)fn;

    void *pA = nullptr, *pB = nullptr;
    cudaGetSymbolAddress(&pA, g_A2);
    cudaGetSymbolAddress(&pB, g_B2);

    CUtensorMap tmaA, tmaB;
    {
        cuuint64_t dims[3]    = {DD, ROWS, 2};
        cuuint64_t strides[2] = {DD * 2ull, (cuuint64_t)ROWS * DD * 2ull};
        cuuint32_t box[3]     = {KC, 128, 1};
        cuuint32_t es[3]      = {1, 1, 1};
        encode(&tmaA, CU_TENSOR_MAP_DATA_TYPE_UINT16, 3, pA, dims, strides, box, es,
               CU_TENSOR_MAP_INTERLEAVE_NONE, CU_TENSOR_MAP_SWIZZLE_128B,
               CU_TENSOR_MAP_L2_PROMOTION_L2_128B, CU_TENSOR_MAP_FLOAT_OOB_FILL_NONE);
    }
    {
        cuuint64_t dims[3]    = {DD, COLS2, 2};
        cuuint64_t strides[2] = {DD * 2ull, (cuuint64_t)COLS2 * DD * 2ull};
        cuuint32_t box[3]     = {KC, 128, 1};
        cuuint32_t es[3]      = {1, 1, 1};
        encode(&tmaB, CU_TENSOR_MAP_DATA_TYPE_UINT16, 3, pB, dims, strides, box, es,
               CU_TENSOR_MAP_INTERLEAVE_NONE, CU_TENSOR_MAP_SWIZZLE_128B,
               CU_TENSOR_MAP_L2_PROMOTION_L2_128B, CU_TENSOR_MAP_FLOAT_OOB_FILL_NONE);
    }

    split_all_kernel<<<ROWS + COLS2 / 32 * (DD / 32), 256>>>(enc, wq, wk);
    gemm_mma_kernel<<<dim3(COLS2 / 128, ROWS / 128), 256, SMEM_TOTAL>>>(tmaA, tmaB, bq, bk, mask);
    logits_softmax_kernel<<<BB, 1024>>>(mask, out);
}

// round 12
// speedup vs baseline: 3.0162x; 1.0419x over previous
#include <cuda_runtime.h>
#include <cuda_fp16.h>
#include <cuda.h>
#include <cstdint>

// ---------------- problem shapes ----------------
#define BB 32
#define AA 32
#define SSQ 128
#define DD 1024
#define NHQ 1024                   // N*H
#define COLS2 2048                 // Q cols + K cols
#define ROWS 1024                  // B*A
#define ENC_ROW_STRIDE ((size_t)SSQ * DD)

#define LO_SCALE 256.0f
#define LO_INV   (1.0f / 256.0f)

// ---------------- device scratch (no allocs allowed) ----------------
__device__ __half g_A2[2][ROWS * DD];     // [hi/lo][row][k]   (CLS splits, lo *256)
__device__ __half g_B2[2][COLS2 * DD];    // [hi/lo][col][k]   (W^T splits, lo *256)
__device__ float g_lpart[16 * ROWS];      // [colTile][row] partial logits

// ---------------- split helper ----------------
__device__ __forceinline__ void split2(float x, __half& h, __half& l) {
    h = __float2half_rn(x);
    float r = x - __half2float(h);
    l = __float2half_rn(r * LO_SCALE);
}

// ---------------- kernel 1: fused splits (CLS + W) ----------------
// blocks [0, ROWS): CLS rows. blocks [ROWS, ROWS+1024): W 64d x 32n transpose tiles.
__global__ void __launch_bounds__(256, 1)
split_all_kernel(const float* __restrict__ enc,
                 const float* __restrict__ wq, const float* __restrict__ wk)
{
    int bx = blockIdx.x;
    int tid = threadIdx.x;
    if (bx < ROWS) {
        // ---- CLS rows -> 2 fp16 planes ----
        int r = bx;
        float4 v = reinterpret_cast<const float4*>(enc + (size_t)r * ENC_ROW_STRIDE)[tid];
        float xs[4] = {v.x, v.y, v.z, v.w};
        ushort4 ph, pl;
        unsigned short* hp = &ph.x; unsigned short* lp = &pl.x;
#pragma unroll
        for (int i = 0; i < 4; i++) {
            __half h, l;
            split2(xs[i], h, l);
            hp[i] = __half_as_ushort(h);
            lp[i] = __half_as_ushort(l);
        }
        size_t o = (size_t)r * DD + tid * 4;
        *reinterpret_cast<ushort4*>(&g_A2[0][o]) = ph;
        *reinterpret_cast<ushort4*>(&g_A2[1][o]) = pl;
    } else {
        // ---- W split + transpose ([d][n] -> [col][k]), 64d x 32n tile ----
        // row stride 68 halves = 136 bytes: 8-byte aligned for ushort4 reads,
        // 2-way bank conflicts on the write phase (34 banks mod 32).
        __shared__ __half sh[2][32][68];
        int idx = bx - ROWS;               // 0..1023
        int c0 = (idx & 63) * 32;          // global col tile (0..2047)
        int d0 = (idx >> 6) * 64;          // d tile (0..960)
        int tx = tid & 31;
        int ty = tid >> 5;                 // 0..7
        const float* W = (c0 < NHQ) ? wq : wk;
        int nb = (c0 < NHQ) ? c0 : (c0 - NHQ);
#pragma unroll
        for (int i = 0; i < 8; i++) {
            int dl = ty + i * 8;           // 0..63
            float x = W[(size_t)(d0 + dl) * NHQ + nb + tx];
            __half h, l;
            split2(x, h, l);
            sh[0][tx][dl] = h;
            sh[1][tx][dl] = l;
        }
        __syncthreads();
#pragma unroll
        for (int j = 0; j < 2; j++) {
            int idx2 = tid + j * 256;      // 0..511
            int col = idx2 >> 4;           // 0..31
            int kq  = idx2 & 15;           // ushort4 chunk (4 k each)
            size_t o = (size_t)(c0 + col) * DD + d0 + kq * 4;
#pragma unroll
            for (int p = 0; p < 2; p++) {
                ushort4 v = *reinterpret_cast<const ushort4*>(&sh[p][col][kq * 4]);
                *reinterpret_cast<ushort4*>(&g_B2[p][o]) = v;
            }
        }
    }
}

// ---------------- GEMM: TMA + ldmatrix + mma.sync + fused logits partials ----------------
#define KC 64
#define NCHUNK (DD / KC)                 // 16
#define TILE_BYTES 16384                 // one 128x128B plane tile
#define STAGE_BYTES (4 * TILE_BYTES)     // A-hi, A-lo, B-hi, B-lo = 64 KB
#define NSTAGE 3
#define SMEM_TILES 1024
#define SMEM_TOTAL (SMEM_TILES + NSTAGE * STAGE_BYTES)   // 197632

__device__ __forceinline__ uint32_t smem_u32(const void* p) {
    uint32_t a;
    asm("{ .reg .u64 t; cvta.to.shared.u64 t, %1; cvt.u32.u64 %0, t; }" : "=r"(a) : "l"(p));
    return a;
}
#define MBAR_INIT(mb, n)  asm volatile("mbarrier.init.shared.b64 [%0], %1;" :: "r"((uint32_t)(mb)), "r"((uint32_t)(n)) : "memory")
#define MBAR_EXPECT_TX(mb, bytes) asm volatile("mbarrier.arrive.expect_tx.shared.b64 _, [%0], %1;" :: "r"((uint32_t)(mb)), "r"((uint32_t)(bytes)) : "memory")
#define MBAR_WAIT(mb, ph) do {                                                          \
    uint32_t _mb = (uint32_t)(mb); uint32_t _p = (uint32_t)(ph); uint32_t _done;        \
    asm volatile("{\n\t.reg .pred p;\n\t"                                               \
        "mbarrier.try_wait.parity.acquire.cta.shared::cta.b64 p, [%1], %2;\n\t"         \
        "selp.b32 %0, 1, 0, p;\n\t}" : "=r"(_done) : "r"(_mb), "r"(_p) : "memory");     \
    if (!_done) {                                                                       \
        asm volatile("{\n\t.reg .pred P1;\n\t"                                          \
            "WL_%=:\n\t"                                                                \
            "mbarrier.try_wait.parity.acquire.cta.shared::cta.b64 P1, [%0], %1, 0x989680;\n\t" \
            "@P1 bra.uni WD_%=;\n\t"                                                    \
            "bra.uni WL_%=;\n\t"                                                        \
            "WD_%=:\n\t}" :: "r"(_mb), "r"(_p) : "memory");                             \
    }                                                                                   \
} while (0)

#define TMA_LOAD_3D(sm, mp, x, y, z, mb)                                                \
    asm volatile("cp.async.bulk.tensor.3d.shared::cta.global.tile.mbarrier::complete_tx::bytes " \
        "[%0], [%1, {%2, %3, %4}], [%5];"                                               \
        :: "r"((uint32_t)(sm)), "l"(mp), "r"((int)(x)), "r"((int)(y)), "r"((int)(z)),   \
           "r"((uint32_t)(mb)) : "memory")

#define LDMATRIX_X4(r0, r1, r2, r3, a)                                                  \
    asm volatile("ldmatrix.sync.aligned.m8n8.x4.shared.b16 {%0,%1,%2,%3}, [%4];"        \
        : "=r"(r0), "=r"(r1), "=r"(r2), "=r"(r3) : "r"(a))
#define LDMATRIX_X2(r0, r1, a)                                                          \
    asm volatile("ldmatrix.sync.aligned.m8n8.x2.shared.b16 {%0,%1}, [%2];"              \
        : "=r"(r0), "=r"(r1) : "r"(a))

__device__ __forceinline__ void mma_f16(float* c, const uint32_t* a, const uint32_t* b) {
    asm volatile(
        "mma.sync.aligned.m16n8k16.row.col.f32.f16.f16.f32 "
        "{%0,%1,%2,%3}, {%4,%5,%6,%7}, {%8,%9}, {%0,%1,%2,%3};"
        : "+f"(c[0]), "+f"(c[1]), "+f"(c[2]), "+f"(c[3])
        : "r"(a[0]), "r"(a[1]), "r"(a[2]), "r"(a[3]), "r"(b[0]), "r"(b[1]));
}

// Grid (16, 8): blockIdx.x = 64-col range of BOTH Q and K; blockIdx.y = 128-row tile.
// B smem rows 0-63 = Q cols [c0, c0+64), rows 64-127 = K cols [c0, c0+64).
__global__ void __launch_bounds__(256, 1)
gemm_mma_kernel(const __grid_constant__ CUtensorMap tma_a,
                const __grid_constant__ CUtensorMap tma_b,
                const float* __restrict__ bq, const float* __restrict__ bk,
                const int* __restrict__ mask)
{
    extern __shared__ char smem[];
    const uint32_t sb = smem_u32(smem);

    const int tid = threadIdx.x;
    const int wid = tid >> 5, lane = tid & 31;
    const int g = lane >> 2, t = lane & 3;
    const int wr = wid >> 2;                  // 0..1 -> m offset wr*64
    const int wc = wid & 3;                   // 0..3 -> B rows wc*32 (wc<2: Q, wc>=2: K)
    const int tileR = blockIdx.y * 128;
    const int c0 = blockIdx.x * 64;           // col range within NHQ

    if (tid == 0) {
#pragma unroll
        for (int s = 0; s < NSTAGE; s++) MBAR_INIT(sb + s * 8, 1);
    }
    __syncthreads();
    if (tid == 0) {
#pragma unroll
        for (int s = 0; s < NSTAGE; s++) {
            uint32_t stg = sb + SMEM_TILES + s * STAGE_BYTES;
            MBAR_EXPECT_TX(sb + s * 8, STAGE_BYTES);
#pragma unroll
            for (int p = 0; p < 2; p++) {
                TMA_LOAD_3D(stg + p * TILE_BYTES, &tma_a, s * KC, tileR, p, sb + s * 8);
                uint32_t bt = stg + (2 + p) * TILE_BYTES;
                TMA_LOAD_3D(bt,        &tma_b, s * KC, c0,       p, sb + s * 8);  // Q cols -> rows 0-63
                TMA_LOAD_3D(bt + 8192, &tma_b, s * KC, NHQ + c0, p, sb + s * 8);  // K cols -> rows 64-127
            }
        }
    }

    // per-lane ldmatrix address components (swizzle xor depends only on lane&7)
    const int xr = (lane & 7) << 4;
    const int a_row_local = (lane & 7) + ((lane >> 3) & 1) * 8;
    const int a_kh16 = ((lane >> 4) & 1) * 16;
    const int b_row_local = lane & 7;
    const int b_kh16 = ((lane >> 3) & 1) * 16;

    uint32_t aro[4], bro[4];
#pragma unroll
    for (int mt = 0; mt < 4; mt++) aro[mt] = (uint32_t)(wr * 64 + mt * 16 + a_row_local) * 128;
#pragma unroll
    for (int nt = 0; nt < 4; nt++) bro[nt] = (uint32_t)(wc * 32 + nt * 8 + b_row_local) * 128;

    float acc0[4][4][4];
    float acc1[4][4][4];
#pragma unroll
    for (int i = 0; i < 4; i++)
#pragma unroll
        for (int j = 0; j < 4; j++)
#pragma unroll
            for (int r = 0; r < 4; r++) { acc0[i][j][r] = 0.f; acc1[i][j][r] = 0.f; }

    for (int c = 0; c < NCHUNK; c++) {
        const int s = c % NSTAGE;
        MBAR_WAIT(sb + s * 8, (c / NSTAGE) & 1);
        const uint32_t stg = sb + SMEM_TILES + (uint32_t)s * STAGE_BYTES;

#pragma unroll
        for (int ks = 0; ks < 4; ks++) {
            const uint32_t akt = (uint32_t)((ks * 32 + a_kh16) ^ xr);
            const uint32_t bkt = (uint32_t)((ks * 32 + b_kh16) ^ xr);
            uint32_t ah[4][4], al[4][4];
            uint32_t bh[4][2], bl[4][2];
#pragma unroll
            for (int mt = 0; mt < 4; mt++) {
                LDMATRIX_X4(ah[mt][0], ah[mt][1], ah[mt][2], ah[mt][3],
                            stg + 0 * TILE_BYTES + aro[mt] + akt);
                LDMATRIX_X4(al[mt][0], al[mt][1], al[mt][2], al[mt][3],
                            stg + 1 * TILE_BYTES + aro[mt] + akt);
            }
#pragma unroll
            for (int nt = 0; nt < 4; nt++) {
                LDMATRIX_X2(bh[nt][0], bh[nt][1], stg + 2 * TILE_BYTES + bro[nt] + bkt);
                LDMATRIX_X2(bl[nt][0], bl[nt][1], stg + 3 * TILE_BYTES + bro[nt] + bkt);
            }
#pragma unroll
            for (int mt = 0; mt < 4; mt++)
#pragma unroll
                for (int nt = 0; nt < 4; nt++) {
                    mma_f16(acc0[mt][nt], ah[mt], bh[nt]);
                    mma_f16(acc1[mt][nt], ah[mt], bl[nt]);
                    mma_f16(acc1[mt][nt], al[mt], bh[nt]);
                }
        }
        __syncthreads();
        if (c + NSTAGE < NCHUNK && tid == 0) {
            uint32_t dst = sb + SMEM_TILES + (uint32_t)s * STAGE_BYTES;
            MBAR_EXPECT_TX(sb + s * 8, STAGE_BYTES);
            int k0 = (c + NSTAGE) * KC;
#pragma unroll
            for (int p = 0; p < 2; p++) {
                TMA_LOAD_3D(dst + p * TILE_BYTES, &tma_a, k0, tileR, p, sb + s * 8);
                uint32_t bt = dst + (2 + p) * TILE_BYTES;
                TMA_LOAD_3D(bt,        &tma_b, k0, c0,       p, sb + s * 8);
                TMA_LOAD_3D(bt + 8192, &tma_b, k0, NHQ + c0, p, sb + s * 8);
            }
        }
    }

    // ---------------- epilogue: Q/K tiles to smem, ksum, CTA-local logit partials ----------------
    float* fsm = reinterpret_cast<float*>(smem);
    float* smQ = fsm;                 // [128][66]
    float* smK = fsm + 128 * 66;      // [128][66]
    float* smS = fsm + 2 * 128 * 66;  // [4][64] per-batch ksum

    const bool isK = (wc >= 2);
    const float* __restrict__ bias = isK ? bk : bq;
    float* dst = isK ? smK : smQ;

#pragma unroll
    for (int mt = 0; mt < 4; mt++) {
        int r0 = wr * 64 + mt * 16 + g;        // local row
        int r1 = r0 + 8;
        float m0 = (float)mask[tileR + r0];
        float m1 = (float)mask[tileR + r1];
#pragma unroll
        for (int nt = 0; nt < 4; nt++) {
            int cl = (wc & 1) * 32 + nt * 8 + t * 2;   // local col 0..62
            float b0 = bias[c0 + cl], b1 = bias[c0 + cl + 1];
            float v0 = acc0[mt][nt][0] + acc1[mt][nt][0] * LO_INV;
            float v1 = acc0[mt][nt][1] + acc1[mt][nt][1] * LO_INV;
            float v2 = acc0[mt][nt][2] + acc1[mt][nt][2] * LO_INV;
            float v3 = acc0[mt][nt][3] + acc1[mt][nt][3] * LO_INV;
            float2 o0, o1;
            o0.x = (v0 + b0) * m0;
            o0.y = (v1 + b1) * m0;
            o1.x = (v2 + b0) * m1;
            o1.y = (v3 + b1) * m1;
            *reinterpret_cast<float2*>(&dst[r0 * 66 + cl]) = o0;
            *reinterpret_cast<float2*>(&dst[r1 * 66 + cl]) = o1;
        }
    }
    __syncthreads();

    // per-batch ksum over local K tile (4 batches of 32 rows)
    {
        int batch = tid >> 6;          // 0..3
        int col   = tid & 63;          // 0..63
        float s = 0.f;
#pragma unroll
        for (int i = 0; i < 32; i++)
            s += smK[(batch * 32 + i) * 66 + col];
        smS[batch * 64 + col] = s;
    }
    __syncthreads();

    // logit partial per row: sum_c Q[x,c] * (ksum_b[c] - K[x,c])
    if (tid < 128) {
        int row = tid;
        int bl = row >> 5;
        float s = 0.f;
#pragma unroll
        for (int cc = 0; cc < 64; cc++)
            s += smQ[row * 66 + cc] * (smS[bl * 64 + cc] - smK[row * 66 + cc]);
        g_lpart[blockIdx.x * ROWS + tileR + row] = s;
    }
}

// ---------------- kernel 3: softmax (32 blocks x 32 threads) ----------------
__global__ void softmax_kernel(const int* __restrict__ mask, float* __restrict__ out)
{
    int b = blockIdx.x;
    int x = threadIdx.x;
    int row = b * AA + x;
    float l = 0.f;
#pragma unroll
    for (int ct = 0; ct < 16; ct++)
        l += g_lpart[ct * ROWS + row];
    float m = (float)mask[row];
    l += (1.0f - m) * -100000.0f;
    float mx = l;
#pragma unroll
    for (int o = 16; o > 0; o >>= 1) mx = fmaxf(mx, __shfl_xor_sync(0xffffffffu, mx, o));
    float e = expf(l - mx);
    float se = e;
#pragma unroll
    for (int o = 16; o > 0; o >>= 1) se += __shfl_xor_sync(0xffffffffu, se, o);
    out[row] = e / se;
}

// ---------------- host: tensor map construction ----------------
typedef CUresult (*EncodeTiledFn)(
    CUtensorMap*, CUtensorMapDataType, cuuint32_t, void*,
    const cuuint64_t*, const cuuint64_t*, const cuuint32_t*, const cuuint32_t*,
    CUtensorMapInterleave, CUtensorMapSwizzle, CUtensorMapL2promotion, CUtensorMapFloatOOBfill);

extern "C" void kernel_launch(void* const* d_in, const int* in_sizes, int n_in,
                              void* d_out, int out_size)
{
    const float* enc  = (const float*)d_in[0];
    const int*   mask = (const int*)  d_in[1];
    const float* wq   = (const float*)d_in[2];
    const float* bq   = (const float*)d_in[3];
    const float* wk   = (const float*)d_in[4];
    const float* bk   = (const float*)d_in[5];
    float* out = (float*)d_out;

    cudaFuncSetAttribute(gemm_mma_kernel, cudaFuncAttributeMaxDynamicSharedMemorySize, SMEM_TOTAL);

    void* fn = nullptr;
    cudaDriverEntryPointQueryResult qr;
    cudaGetDriverEntryPointByVersion("cuTensorMapEncodeTiled", &fn, 12000,
                                     cudaEnableDefault, &qr);
    EncodeTiledFn encode = (EncodeTiledFn)fn;

    void *pA = nullptr, *pB = nullptr;
    cudaGetSymbolAddress(&pA, g_A2);
    cudaGetSymbolAddress(&pB, g_B2);

    CUtensorMap tmaA, tmaB;
    {
        cuuint64_t dims[3]    = {DD, ROWS, 2};
        cuuint64_t strides[2] = {DD * 2ull, (cuuint64_t)ROWS * DD * 2ull};
        cuuint32_t box[3]     = {KC, 128, 1};
        cuuint32_t es[3]      = {1, 1, 1};
        encode(&tmaA, CU_TENSOR_MAP_DATA_TYPE_UINT16, 3, pA, dims, strides, box, es,
               CU_TENSOR_MAP_INTERLEAVE_NONE, CU_TENSOR_MAP_SWIZZLE_128B,
               CU_TENSOR_MAP_L2_PROMOTION_L2_128B, CU_TENSOR_MAP_FLOAT_OOB_FILL_NONE);
    }
    {
        cuuint64_t dims[3]    = {DD, COLS2, 2};
        cuuint64_t strides[2] = {DD * 2ull, (cuuint64_t)COLS2 * DD * 2ull};
        cuuint32_t box[3]     = {KC, 64, 1};
        cuuint32_t es[3]      = {1, 1, 1};
        encode(&tmaB, CU_TENSOR_MAP_DATA_TYPE_UINT16, 3, pB, dims, strides, box, es,
               CU_TENSOR_MAP_INTERLEAVE_NONE, CU_TENSOR_MAP_SWIZZLE_128B,
               CU_TENSOR_MAP_L2_PROMOTION_L2_128B, CU_TENSOR_MAP_FLOAT_OOB_FILL_NONE);
    }

    split_all_kernel<<<ROWS + 1024, 256>>>(enc, wq, wk);
    gemm_mma_kernel<<<dim3(16, 8), 256, SMEM_TOTAL>>>(tmaA, tmaB, bq, bk, mask);
    softmax_kernel<<<BB, 32>>>(mask, out);
}

// round 13
// speedup vs baseline: 3.0796x; 1.0210x over previous
#include <cuda_runtime.h>
#include <cuda_fp16.h>
#include <cuda.h>
#include <cstdint>

// ---------------- problem shapes ----------------
#define BB 32
#define AA 32
#define SSQ 128
#define DD 1024
#define NHQ 1024                   // N*H
#define COLS2 2048                 // Q cols + K cols
#define ROWS 1024                  // B*A
#define ENC_ROW_STRIDE ((size_t)SSQ * DD)

#define LO_SCALE 256.0f
#define LO_INV   (1.0f / 256.0f)

// ---------------- device scratch (no allocs allowed) ----------------
__device__ __half g_A2[2][ROWS * DD];     // [hi/lo][row][k]   (CLS splits, lo *256)
__device__ __half g_B2[2][COLS2 * DD];    // [hi/lo][col][k]   (W^T splits, lo *256)
__device__ float g_lpart[16 * ROWS];      // [colTile][row] partial logits

// ---------------- split helper ----------------
__device__ __forceinline__ void split2(float x, __half& h, __half& l) {
    h = __float2half_rn(x);
    float r = x - __half2float(h);
    l = __float2half_rn(r * LO_SCALE);
}

// ---------------- kernel 1: fused splits (CLS + W) ----------------
// blocks [0, ROWS): CLS rows. blocks [ROWS, ROWS+1024): W 64d x 32n transpose tiles.
__global__ void __launch_bounds__(256, 1)
split_all_kernel(const float* __restrict__ enc,
                 const float* __restrict__ wq, const float* __restrict__ wk)
{
    int bx = blockIdx.x;
    int tid = threadIdx.x;
    if (bx < ROWS) {
        // ---- CLS rows -> 2 fp16 planes ----
        int r = bx;
        float4 v = reinterpret_cast<const float4*>(enc + (size_t)r * ENC_ROW_STRIDE)[tid];
        float xs[4] = {v.x, v.y, v.z, v.w};
        ushort4 ph, pl;
        unsigned short* hp = &ph.x; unsigned short* lp = &pl.x;
#pragma unroll
        for (int i = 0; i < 4; i++) {
            __half h, l;
            split2(xs[i], h, l);
            hp[i] = __half_as_ushort(h);
            lp[i] = __half_as_ushort(l);
        }
        size_t o = (size_t)r * DD + tid * 4;
        *reinterpret_cast<ushort4*>(&g_A2[0][o]) = ph;
        *reinterpret_cast<ushort4*>(&g_A2[1][o]) = pl;
    } else {
        // ---- W split + transpose ([d][n] -> [col][k]), 64d x 32n tile ----
        // row stride 68 halves = 136 bytes: 8-byte aligned for ushort4 reads,
        // 2-way bank conflicts on the write phase (34 banks mod 32).
        __shared__ __half sh[2][32][68];
        int idx = bx - ROWS;               // 0..1023
        int c0 = (idx & 63) * 32;          // global col tile (0..2047)
        int d0 = (idx >> 6) * 64;          // d tile (0..960)
        int tx = tid & 31;
        int ty = tid >> 5;                 // 0..7
        const float* W = (c0 < NHQ) ? wq : wk;
        int nb = (c0 < NHQ) ? c0 : (c0 - NHQ);
#pragma unroll
        for (int i = 0; i < 8; i++) {
            int dl = ty + i * 8;           // 0..63
            float x = W[(size_t)(d0 + dl) * NHQ + nb + tx];
            __half h, l;
            split2(x, h, l);
            sh[0][tx][dl] = h;
            sh[1][tx][dl] = l;
        }
        __syncthreads();
#pragma unroll
        for (int j = 0; j < 2; j++) {
            int idx2 = tid + j * 256;      // 0..511
            int col = idx2 >> 4;           // 0..31
            int kq  = idx2 & 15;           // ushort4 chunk (4 k each)
            size_t o = (size_t)(c0 + col) * DD + d0 + kq * 4;
#pragma unroll
            for (int p = 0; p < 2; p++) {
                ushort4 v = *reinterpret_cast<const ushort4*>(&sh[p][col][kq * 4]);
                *reinterpret_cast<ushort4*>(&g_B2[p][o]) = v;
            }
        }
    }
}

// ---------------- GEMM: TMA + ldmatrix + mma.sync + fused logits partials ----------------
#define KC 64
#define NCHUNK (DD / KC)                 // 16
#define TILE_BYTES 16384                 // one 128x128B plane tile
#define STAGE_BYTES (4 * TILE_BYTES)     // A-hi, A-lo, B-hi, B-lo = 64 KB
#define NSTAGE 3
#define SMEM_TILES 1024
#define SMEM_TOTAL (SMEM_TILES + NSTAGE * STAGE_BYTES)   // 197632

__device__ __forceinline__ uint32_t smem_u32(const void* p) {
    uint32_t a;
    asm("{ .reg .u64 t; cvta.to.shared.u64 t, %1; cvt.u32.u64 %0, t; }" : "=r"(a) : "l"(p));
    return a;
}
#define MBAR_INIT(mb, n)  asm volatile("mbarrier.init.shared.b64 [%0], %1;" :: "r"((uint32_t)(mb)), "r"((uint32_t)(n)) : "memory")
#define MBAR_EXPECT_TX(mb, bytes) asm volatile("mbarrier.arrive.expect_tx.shared.b64 _, [%0], %1;" :: "r"((uint32_t)(mb)), "r"((uint32_t)(bytes)) : "memory")
#define MBAR_WAIT(mb, ph) do {                                                          \
    uint32_t _mb = (uint32_t)(mb); uint32_t _p = (uint32_t)(ph); uint32_t _done;        \
    asm volatile("{\n\t.reg .pred p;\n\t"                                               \
        "mbarrier.try_wait.parity.acquire.cta.shared::cta.b64 p, [%1], %2;\n\t"         \
        "selp.b32 %0, 1, 0, p;\n\t}" : "=r"(_done) : "r"(_mb), "r"(_p) : "memory");     \
    if (!_done) {                                                                       \
        asm volatile("{\n\t.reg .pred P1;\n\t"                                          \
            "WL_%=:\n\t"                                                                \
            "mbarrier.try_wait.parity.acquire.cta.shared::cta.b64 P1, [%0], %1, 0x989680;\n\t" \
            "@P1 bra.uni WD_%=;\n\t"                                                    \
            "bra.uni WL_%=;\n\t"                                                        \
            "WD_%=:\n\t}" :: "r"(_mb), "r"(_p) : "memory");                             \
    }                                                                                   \
} while (0)

#define TMA_LOAD_3D(sm, mp, x, y, z, mb)                                                \
    asm volatile("cp.async.bulk.tensor.3d.shared::cta.global.tile.mbarrier::complete_tx::bytes " \
        "[%0], [%1, {%2, %3, %4}], [%5];"                                               \
        :: "r"((uint32_t)(sm)), "l"(mp), "r"((int)(x)), "r"((int)(y)), "r"((int)(z)),   \
           "r"((uint32_t)(mb)) : "memory")

#define LDMATRIX_X4(r0, r1, r2, r3, a)                                                  \
    asm volatile("ldmatrix.sync.aligned.m8n8.x4.shared.b16 {%0,%1,%2,%3}, [%4];"        \
        : "=r"(r0), "=r"(r1), "=r"(r2), "=r"(r3) : "r"(a))
#define LDMATRIX_X2(r0, r1, a)                                                          \
    asm volatile("ldmatrix.sync.aligned.m8n8.x2.shared.b16 {%0,%1}, [%2];"              \
        : "=r"(r0), "=r"(r1) : "r"(a))

__device__ __forceinline__ void mma_f16(float* c, const uint32_t* a, const uint32_t* b) {
    asm volatile(
        "mma.sync.aligned.m16n8k16.row.col.f32.f16.f16.f32 "
        "{%0,%1,%2,%3}, {%4,%5,%6,%7}, {%8,%9}, {%0,%1,%2,%3};"
        : "+f"(c[0]), "+f"(c[1]), "+f"(c[2]), "+f"(c[3])
        : "r"(a[0]), "r"(a[1]), "r"(a[2]), "r"(a[3]), "r"(b[0]), "r"(b[1]));
}

// Grid (16, 8): blockIdx.x = 64-col range of BOTH Q and K; blockIdx.y = 128-row tile.
// B smem rows 0-63 = Q cols [c0, c0+64), rows 64-127 = K cols [c0, c0+64).
__global__ void __launch_bounds__(256, 1)
gemm_mma_kernel(const __grid_constant__ CUtensorMap tma_a,
                const __grid_constant__ CUtensorMap tma_b,
                const float* __restrict__ bq, const float* __restrict__ bk,
                const int* __restrict__ mask)
{
    extern __shared__ char smem[];
    const uint32_t sb = smem_u32(smem);

    const int tid = threadIdx.x;
    const int wid = tid >> 5, lane = tid & 31;
    const int g = lane >> 2, t = lane & 3;
    const int wr = wid >> 2;                  // 0..1 -> m offset wr*64
    const int wc = wid & 3;                   // 0..3 -> B rows wc*32 (wc<2: Q, wc>=2: K)
    const int tileR = blockIdx.y * 128;
    const int c0 = blockIdx.x * 64;           // col range within NHQ

    if (tid == 0) {
#pragma unroll
        for (int s = 0; s < NSTAGE; s++) MBAR_INIT(sb + s * 8, 1);
    }
    __syncthreads();
    if (tid == 0) {
#pragma unroll
        for (int s = 0; s < NSTAGE; s++) {
            uint32_t stg = sb + SMEM_TILES + s * STAGE_BYTES;
            MBAR_EXPECT_TX(sb + s * 8, STAGE_BYTES);
#pragma unroll
            for (int p = 0; p < 2; p++) {
                TMA_LOAD_3D(stg + p * TILE_BYTES, &tma_a, s * KC, tileR, p, sb + s * 8);
                uint32_t bt = stg + (2 + p) * TILE_BYTES;
                TMA_LOAD_3D(bt,        &tma_b, s * KC, c0,       p, sb + s * 8);  // Q cols -> rows 0-63
                TMA_LOAD_3D(bt + 8192, &tma_b, s * KC, NHQ + c0, p, sb + s * 8);  // K cols -> rows 64-127
            }
        }
    }

    // per-lane ldmatrix address components (swizzle xor depends only on lane&7)
    const int xr = (lane & 7) << 4;
    const int a_row_local = (lane & 7) + ((lane >> 3) & 1) * 8;
    const int a_kh16 = ((lane >> 4) & 1) * 16;
    const int b_row_local = lane & 7;
    const int b_kh16 = ((lane >> 3) & 1) * 16;

    uint32_t aro[4], bro[4];
#pragma unroll
    for (int mt = 0; mt < 4; mt++) aro[mt] = (uint32_t)(wr * 64 + mt * 16 + a_row_local) * 128;
#pragma unroll
    for (int nt = 0; nt < 4; nt++) bro[nt] = (uint32_t)(wc * 32 + nt * 8 + b_row_local) * 128;

    float acc0[4][4][4];
    float acc1[4][4][4];
#pragma unroll
    for (int i = 0; i < 4; i++)
#pragma unroll
        for (int j = 0; j < 4; j++)
#pragma unroll
            for (int r = 0; r < 4; r++) { acc0[i][j][r] = 0.f; acc1[i][j][r] = 0.f; }

    for (int c = 0; c < NCHUNK; c++) {
        const int s = c % NSTAGE;
        MBAR_WAIT(sb + s * 8, (c / NSTAGE) & 1);
        const uint32_t stg = sb + SMEM_TILES + (uint32_t)s * STAGE_BYTES;

#pragma unroll
        for (int ks = 0; ks < 4; ks++) {
            const uint32_t akt = (uint32_t)((ks * 32 + a_kh16) ^ xr);
            const uint32_t bkt = (uint32_t)((ks * 32 + b_kh16) ^ xr);
            uint32_t ah[4][4], al[4][4];
            uint32_t bh[4][2], bl[4][2];
#pragma unroll
            for (int mt = 0; mt < 4; mt++) {
                LDMATRIX_X4(ah[mt][0], ah[mt][1], ah[mt][2], ah[mt][3],
                            stg + 0 * TILE_BYTES + aro[mt] + akt);
                LDMATRIX_X4(al[mt][0], al[mt][1], al[mt][2], al[mt][3],
                            stg + 1 * TILE_BYTES + aro[mt] + akt);
            }
#pragma unroll
            for (int nt = 0; nt < 4; nt++) {
                LDMATRIX_X2(bh[nt][0], bh[nt][1], stg + 2 * TILE_BYTES + bro[nt] + bkt);
                LDMATRIX_X2(bl[nt][0], bl[nt][1], stg + 3 * TILE_BYTES + bro[nt] + bkt);
            }
#pragma unroll
            for (int mt = 0; mt < 4; mt++)
#pragma unroll
                for (int nt = 0; nt < 4; nt++) {
                    mma_f16(acc0[mt][nt], ah[mt], bh[nt]);
                    mma_f16(acc1[mt][nt], ah[mt], bl[nt]);
                    mma_f16(acc1[mt][nt], al[mt], bh[nt]);
                }
        }
        __syncthreads();
        if (c + NSTAGE < NCHUNK && tid == 0) {
            uint32_t dst = sb + SMEM_TILES + (uint32_t)s * STAGE_BYTES;
            MBAR_EXPECT_TX(sb + s * 8, STAGE_BYTES);
            int k0 = (c + NSTAGE) * KC;
#pragma unroll
            for (int p = 0; p < 2; p++) {
                TMA_LOAD_3D(dst + p * TILE_BYTES, &tma_a, k0, tileR, p, sb + s * 8);
                uint32_t bt = dst + (2 + p) * TILE_BYTES;
                TMA_LOAD_3D(bt,        &tma_b, k0, c0,       p, sb + s * 8);
                TMA_LOAD_3D(bt + 8192, &tma_b, k0, NHQ + c0, p, sb + s * 8);
            }
        }
    }

    // ---------------- epilogue: Q/K tiles to smem, ksum, CTA-local logit partials ----------------
    float* fsm = reinterpret_cast<float*>(smem);
    float* smQ = fsm;                 // [128][66]
    float* smK = fsm + 128 * 66;      // [128][66]
    float* smS = fsm + 2 * 128 * 66;  // [4][64] per-batch ksum

    const bool isK = (wc >= 2);
    const float* __restrict__ bias = isK ? bk : bq;
    float* dst = isK ? smK : smQ;

#pragma unroll
    for (int mt = 0; mt < 4; mt++) {
        int r0 = wr * 64 + mt * 16 + g;        // local row
        int r1 = r0 + 8;
        float m0 = (float)mask[tileR + r0];
        float m1 = (float)mask[tileR + r1];
#pragma unroll
        for (int nt = 0; nt < 4; nt++) {
            int cl = (wc & 1) * 32 + nt * 8 + t * 2;   // local col 0..62
            float b0 = bias[c0 + cl], b1 = bias[c0 + cl + 1];
            float v0 = acc0[mt][nt][0] + acc1[mt][nt][0] * LO_INV;
            float v1 = acc0[mt][nt][1] + acc1[mt][nt][1] * LO_INV;
            float v2 = acc0[mt][nt][2] + acc1[mt][nt][2] * LO_INV;
            float v3 = acc0[mt][nt][3] + acc1[mt][nt][3] * LO_INV;
            float2 o0, o1;
            o0.x = (v0 + b0) * m0;
            o0.y = (v1 + b1) * m0;
            o1.x = (v2 + b0) * m1;
            o1.y = (v3 + b1) * m1;
            *reinterpret_cast<float2*>(&dst[r0 * 66 + cl]) = o0;
            *reinterpret_cast<float2*>(&dst[r1 * 66 + cl]) = o1;
        }
    }
    __syncthreads();

    // per-batch ksum over local K tile (4 batches of 32 rows)
    {
        int batch = tid >> 6;          // 0..3
        int col   = tid & 63;          // 0..63
        float s = 0.f;
#pragma unroll
        for (int i = 0; i < 32; i++)
            s += smK[(batch * 32 + i) * 66 + col];
        smS[batch * 64 + col] = s;
    }
    __syncthreads();

    // logit partial per row: sum_c Q[x,c] * (ksum_b[c] - K[x,c])
    if (tid < 128) {
        int row = tid;
        int bl = row >> 5;
        float s = 0.f;
#pragma unroll
        for (int cc = 0; cc < 64; cc++)
            s += smQ[row * 66 + cc] * (smS[bl * 64 + cc] - smK[row * 66 + cc]);
        g_lpart[blockIdx.x * ROWS + tileR + row] = s;
    }
}

// ---------------- kernel 3: softmax (32 blocks x 32 threads) ----------------
__global__ void softmax_kernel(const int* __restrict__ mask, float* __restrict__ out)
{
    int b = blockIdx.x;
    int x = threadIdx.x;
    int row = b * AA + x;
    float l = 0.f;
#pragma unroll
    for (int ct = 0; ct < 16; ct++)
        l += g_lpart[ct * ROWS + row];
    float m = (float)mask[row];
    l += (1.0f - m) * -100000.0f;
    float mx = l;
#pragma unroll
    for (int o = 16; o > 0; o >>= 1) mx = fmaxf(mx, __shfl_xor_sync(0xffffffffu, mx, o));
    float e = expf(l - mx);
    float se = e;
#pragma unroll
    for (int o = 16; o > 0; o >>= 1) se += __shfl_xor_sync(0xffffffffu, se, o);
    out[row] = e / se;
}

// ---------------- host: tensor map construction ----------------
typedef CUresult (*EncodeTiledFn)(
    CUtensorMap*, CUtensorMapDataType, cuuint32_t, void*,
    const cuuint64_t*, const cuuint64_t*, const cuuint32_t*, const cuuint32_t*,
    CUtensorMapInterleave, CUtensorMapSwizzle, CUtensorMapL2promotion, CUtensorMapFloatOOBfill);

extern "C" void kernel_launch(void* const* d_in, const int* in_sizes, int n_in,
                              void* d_out, int out_size)
{
    const float* enc  = (const float*)d_in[0];
    const int*   mask = (const int*)  d_in[1];
    const float* wq   = (const float*)d_in[2];
    const float* bq   = (const float*)d_in[3];
    const float* wk   = (const float*)d_in[4];
    const float* bk   = (const float*)d_in[5];
    float* out = (float*)d_out;

    cudaFuncSetAttribute(gemm_mma_kernel, cudaFuncAttributeMaxDynamicSharedMemorySize, SMEM_TOTAL);

    void* fn = nullptr;
    cudaDriverEntryPointQueryResult qr;
    cudaGetDriverEntryPointByVersion("cuTensorMapEncodeTiled", &fn, 12000,
                                     cudaEnableDefault, &qr);
    EncodeTiledFn encode = (EncodeTiledFn)fn;

    void *pA = nullptr, *pB = nullptr;
    cudaGetSymbolAddress(&pA, g_A2);
    cudaGetSymbolAddress(&pB, g_B2);

    CUtensorMap tmaA, tmaB;
    {
        cuuint64_t dims[3]    = {DD, ROWS, 2};
        cuuint64_t strides[2] = {DD * 2ull, (cuuint64_t)ROWS * DD * 2ull};
        cuuint32_t box[3]     = {KC, 128, 1};
        cuuint32_t es[3]      = {1, 1, 1};
        encode(&tmaA, CU_TENSOR_MAP_DATA_TYPE_UINT16, 3, pA, dims, strides, box, es,
               CU_TENSOR_MAP_INTERLEAVE_NONE, CU_TENSOR_MAP_SWIZZLE_128B,
               CU_TENSOR_MAP_L2_PROMOTION_L2_128B, CU_TENSOR_MAP_FLOAT_OOB_FILL_NONE);
    }
    {
        cuuint64_t dims[3]    = {DD, COLS2, 2};
        cuuint64_t strides[2] = {DD * 2ull, (cuuint64_t)COLS2 * DD * 2ull};
        cuuint32_t box[3]     = {KC, 64, 1};
        cuuint32_t es[3]      = {1, 1, 1};
        encode(&tmaB, CU_TENSOR_MAP_DATA_TYPE_UINT16, 3, pB, dims, strides, box, es,
               CU_TENSOR_MAP_INTERLEAVE_NONE, CU_TENSOR_MAP_SWIZZLE_128B,
               CU_TENSOR_MAP_L2_PROMOTION_L2_128B, CU_TENSOR_MAP_FLOAT_OOB_FILL_NONE);
    }

    split_all_kernel<<<ROWS + 1024, 256>>>(enc, wq, wk);
    gemm_mma_kernel<<<dim3(16, 8), 256, SMEM_TOTAL>>>(tmaA, tmaB, bq, bk, mask);
    softmax_kernel<<<BB, 32>>>(mask, out);
}

// round 16
// speedup vs baseline: 3.1579x; 1.0254x over previous
#include <cuda_runtime.h>
#include <cuda_fp16.h>
#include <cuda.h>
#include <cstdint>

// ---------------- problem shapes ----------------
#define BB 32
#define AA 32
#define SSQ 128
#define DD 1024
#define NHQ 1024                   // N*H
#define COLS2 2048                 // Q cols + K cols
#define ROWS 1024                  // B*A
#define ENC_ROW_STRIDE ((size_t)SSQ * DD)

#define LO_SCALE 256.0f
#define LO_INV   (1.0f / 256.0f)

// ---------------- device scratch (no allocs allowed) ----------------
__device__ __half g_A2[2][ROWS * DD];     // [hi/lo][row][k]   (CLS splits, lo *256)
__device__ __half g_B2[2][COLS2 * DD];    // [hi/lo][col][k]   (W^T splits, lo *256)
__device__ float g_lpart[16 * ROWS];      // [colTile][row] partial logits

// ---------------- split helper ----------------
__device__ __forceinline__ void split2(float x, __half& h, __half& l) {
    h = __float2half_rn(x);
    float r = x - __half2float(h);
    l = __float2half_rn(r * LO_SCALE);
}

// ---------------- kernel 1: fused splits (CLS + W) ----------------
// blocks [0, ROWS): CLS rows. blocks [ROWS, ROWS+1024): W 64d x 32n transpose tiles.
__global__ void __launch_bounds__(256, 1)
split_all_kernel(const float* __restrict__ enc,
                 const float* __restrict__ wq, const float* __restrict__ wk)
{
    int bx = blockIdx.x;
    int tid = threadIdx.x;
    if (bx < ROWS) {
        // ---- CLS rows -> 2 fp16 planes ----
        int r = bx;
        float4 v = reinterpret_cast<const float4*>(enc + (size_t)r * ENC_ROW_STRIDE)[tid];
        float xs[4] = {v.x, v.y, v.z, v.w};
        ushort4 ph, pl;
        unsigned short* hp = &ph.x; unsigned short* lp = &pl.x;
#pragma unroll
        for (int i = 0; i < 4; i++) {
            __half h, l;
            split2(xs[i], h, l);
            hp[i] = __half_as_ushort(h);
            lp[i] = __half_as_ushort(l);
        }
        size_t o = (size_t)r * DD + tid * 4;
        *reinterpret_cast<ushort4*>(&g_A2[0][o]) = ph;
        *reinterpret_cast<ushort4*>(&g_A2[1][o]) = pl;
    } else {
        // ---- W split + transpose ([d][n] -> [col][k]), 64d x 32n tile ----
        // row stride 68 halves = 136 bytes: 8-byte aligned for ushort4 reads,
        // 2-way bank conflicts on the write phase (34 banks mod 32).
        __shared__ __half sh[2][32][68];
        int idx = bx - ROWS;               // 0..1023
        int c0 = (idx & 63) * 32;          // global col tile (0..2047)
        int d0 = (idx >> 6) * 64;          // d tile (0..960)
        int tx = tid & 31;
        int ty = tid >> 5;                 // 0..7
        const float* W = (c0 < NHQ) ? wq : wk;
        int nb = (c0 < NHQ) ? c0 : (c0 - NHQ);
#pragma unroll
        for (int i = 0; i < 8; i++) {
            int dl = ty + i * 8;           // 0..63
            float x = W[(size_t)(d0 + dl) * NHQ + nb + tx];
            __half h, l;
            split2(x, h, l);
            sh[0][tx][dl] = h;
            sh[1][tx][dl] = l;
        }
        __syncthreads();
#pragma unroll
        for (int j = 0; j < 2; j++) {
            int idx2 = tid + j * 256;      // 0..511
            int col = idx2 >> 4;           // 0..31
            int kq  = idx2 & 15;           // ushort4 chunk (4 k each)
            size_t o = (size_t)(c0 + col) * DD + d0 + kq * 4;
#pragma unroll
            for (int p = 0; p < 2; p++) {
                ushort4 v = *reinterpret_cast<const ushort4*>(&sh[p][col][kq * 4]);
                *reinterpret_cast<ushort4*>(&g_B2[p][o]) = v;
            }
        }
    }
}

// ---------------- GEMM: TMA + ldmatrix + mma.sync + fused logits partials ----------------
#define KC 64
#define NCHUNK (DD / KC)                 // 16
#define TILE_BYTES 16384                 // one 128x128B plane tile
#define STAGE_BYTES (4 * TILE_BYTES)     // A-hi, A-lo, B-hi, B-lo = 64 KB
#define NSTAGE 3
#define SMEM_TILES 1024
#define SMEM_TOTAL (SMEM_TILES + NSTAGE * STAGE_BYTES)   // 197632

__device__ __forceinline__ uint32_t smem_u32(const void* p) {
    uint32_t a;
    asm("{ .reg .u64 t; cvta.to.shared.u64 t, %1; cvt.u32.u64 %0, t; }" : "=r"(a) : "l"(p));
    return a;
}
#define MBAR_INIT(mb, n)  asm volatile("mbarrier.init.shared.b64 [%0], %1;" :: "r"((uint32_t)(mb)), "r"((uint32_t)(n)) : "memory")
#define MBAR_EXPECT_TX(mb, bytes) asm volatile("mbarrier.arrive.expect_tx.shared.b64 _, [%0], %1;" :: "r"((uint32_t)(mb)), "r"((uint32_t)(bytes)) : "memory")
#define MBAR_WAIT(mb, ph) do {                                                          \
    uint32_t _mb = (uint32_t)(mb); uint32_t _p = (uint32_t)(ph); uint32_t _done;        \
    asm volatile("{\n\t.reg .pred p;\n\t"                                               \
        "mbarrier.try_wait.parity.acquire.cta.shared::cta.b64 p, [%1], %2;\n\t"         \
        "selp.b32 %0, 1, 0, p;\n\t}" : "=r"(_done) : "r"(_mb), "r"(_p) : "memory");     \
    if (!_done) {                                                                       \
        asm volatile("{\n\t.reg .pred P1;\n\t"                                          \
            "WL_%=:\n\t"                                                                \
            "mbarrier.try_wait.parity.acquire.cta.shared::cta.b64 P1, [%0], %1, 0x989680;\n\t" \
            "@P1 bra.uni WD_%=;\n\t"                                                    \
            "bra.uni WL_%=;\n\t"                                                        \
            "WD_%=:\n\t}" :: "r"(_mb), "r"(_p) : "memory");                             \
    }                                                                                   \
} while (0)

#define TMA_LOAD_3D(sm, mp, x, y, z, mb)                                                \
    asm volatile("cp.async.bulk.tensor.3d.shared::cta.global.tile.mbarrier::complete_tx::bytes " \
        "[%0], [%1, {%2, %3, %4}], [%5];"                                               \
        :: "r"((uint32_t)(sm)), "l"(mp), "r"((int)(x)), "r"((int)(y)), "r"((int)(z)),   \
           "r"((uint32_t)(mb)) : "memory")

#define LDMATRIX_X4(r0, r1, r2, r3, a)                                                  \
    asm volatile("ldmatrix.sync.aligned.m8n8.x4.shared.b16 {%0,%1,%2,%3}, [%4];"        \
        : "=r"(r0), "=r"(r1), "=r"(r2), "=r"(r3) : "r"(a))
#define LDMATRIX_X2(r0, r1, a)                                                          \
    asm volatile("ldmatrix.sync.aligned.m8n8.x2.shared.b16 {%0,%1}, [%2];"              \
        : "=r"(r0), "=r"(r1) : "r"(a))

__device__ __forceinline__ void mma_f16(float* c, const uint32_t* a, const uint32_t* b) {
    asm volatile(
        "mma.sync.aligned.m16n8k16.row.col.f32.f16.f16.f32 "
        "{%0,%1,%2,%3}, {%4,%5,%6,%7}, {%8,%9}, {%0,%1,%2,%3};"
        : "+f"(c[0]), "+f"(c[1]), "+f"(c[2]), "+f"(c[3])
        : "r"(a[0]), "r"(a[1]), "r"(a[2]), "r"(a[3]), "r"(b[0]), "r"(b[1]));
}

// Grid (16, 8): blockIdx.x = 64-col range of BOTH Q and K; blockIdx.y = 128-row tile.
// B smem rows 0-63 = Q cols [c0, c0+64), rows 64-127 = K cols [c0, c0+64).
__global__ void __launch_bounds__(256, 1)
gemm_mma_kernel(const __grid_constant__ CUtensorMap tma_a,
                const __grid_constant__ CUtensorMap tma_b,
                const float* __restrict__ bq, const float* __restrict__ bk,
                const int* __restrict__ mask)
{
    extern __shared__ char smem[];
    const uint32_t sb = smem_u32(smem);

    const int tid = threadIdx.x;
    const int wid = tid >> 5, lane = tid & 31;
    const int g = lane >> 2, t = lane & 3;
    const int wr = wid >> 2;                  // 0..1 -> m offset wr*64
    const int wc = wid & 3;                   // 0..3 -> B rows wc*32 (wc<2: Q, wc>=2: K)
    const int tileR = blockIdx.y * 128;
    const int c0 = blockIdx.x * 64;           // col range within NHQ

    if (tid == 0) {
#pragma unroll
        for (int s = 0; s < NSTAGE; s++) MBAR_INIT(sb + s * 8, 1);
    }
    __syncthreads();
    if (tid == 0) {
#pragma unroll
        for (int s = 0; s < NSTAGE; s++) {
            uint32_t stg = sb + SMEM_TILES + s * STAGE_BYTES;
            MBAR_EXPECT_TX(sb + s * 8, STAGE_BYTES);
#pragma unroll
            for (int p = 0; p < 2; p++) {
                TMA_LOAD_3D(stg + p * TILE_BYTES, &tma_a, s * KC, tileR, p, sb + s * 8);
                uint32_t bt = stg + (2 + p) * TILE_BYTES;
                TMA_LOAD_3D(bt,        &tma_b, s * KC, c0,       p, sb + s * 8);  // Q cols -> rows 0-63
                TMA_LOAD_3D(bt + 8192, &tma_b, s * KC, NHQ + c0, p, sb + s * 8);  // K cols -> rows 64-127
            }
        }
    }

    // per-lane ldmatrix address components (swizzle xor depends only on lane&7)
    const int xr = (lane & 7) << 4;
    const int a_row_local = (lane & 7) + ((lane >> 3) & 1) * 8;
    const int a_kh16 = ((lane >> 4) & 1) * 16;
    const int b_row_local = lane & 7;
    const int b_kh16 = ((lane >> 3) & 1) * 16;

    uint32_t aro[4], bro[4];
#pragma unroll
    for (int mt = 0; mt < 4; mt++) aro[mt] = (uint32_t)(wr * 64 + mt * 16 + a_row_local) * 128;
#pragma unroll
    for (int nt = 0; nt < 4; nt++) bro[nt] = (uint32_t)(wc * 32 + nt * 8 + b_row_local) * 128;

    float acc0[4][4][4];
    float acc1[4][4][4];
#pragma unroll
    for (int i = 0; i < 4; i++)
#pragma unroll
        for (int j = 0; j < 4; j++)
#pragma unroll
            for (int r = 0; r < 4; r++) { acc0[i][j][r] = 0.f; acc1[i][j][r] = 0.f; }

    for (int c = 0; c < NCHUNK; c++) {
        const int s = c % NSTAGE;
        MBAR_WAIT(sb + s * 8, (c / NSTAGE) & 1);
        const uint32_t stg = sb + SMEM_TILES + (uint32_t)s * STAGE_BYTES;

#pragma unroll
        for (int ks = 0; ks < 4; ks++) {
            const uint32_t akt = (uint32_t)((ks * 32 + a_kh16) ^ xr);
            const uint32_t bkt = (uint32_t)((ks * 32 + b_kh16) ^ xr);
            uint32_t ah[4][4], al[4][4];
            uint32_t bh[4][2], bl[4][2];
#pragma unroll
            for (int mt = 0; mt < 4; mt++) {
                LDMATRIX_X4(ah[mt][0], ah[mt][1], ah[mt][2], ah[mt][3],
                            stg + 0 * TILE_BYTES + aro[mt] + akt);
                LDMATRIX_X4(al[mt][0], al[mt][1], al[mt][2], al[mt][3],
                            stg + 1 * TILE_BYTES + aro[mt] + akt);
            }
#pragma unroll
            for (int nt = 0; nt < 4; nt++) {
                LDMATRIX_X2(bh[nt][0], bh[nt][1], stg + 2 * TILE_BYTES + bro[nt] + bkt);
                LDMATRIX_X2(bl[nt][0], bl[nt][1], stg + 3 * TILE_BYTES + bro[nt] + bkt);
            }
#pragma unroll
            for (int mt = 0; mt < 4; mt++)
#pragma unroll
                for (int nt = 0; nt < 4; nt++) {
                    mma_f16(acc0[mt][nt], ah[mt], bh[nt]);
                    mma_f16(acc1[mt][nt], ah[mt], bl[nt]);
                    mma_f16(acc1[mt][nt], al[mt], bh[nt]);
                }
        }
        __syncthreads();
        if (c + NSTAGE < NCHUNK && tid == 0) {
            uint32_t dst = sb + SMEM_TILES + (uint32_t)s * STAGE_BYTES;
            MBAR_EXPECT_TX(sb + s * 8, STAGE_BYTES);
            int k0 = (c + NSTAGE) * KC;
#pragma unroll
            for (int p = 0; p < 2; p++) {
                TMA_LOAD_3D(dst + p * TILE_BYTES, &tma_a, k0, tileR, p, sb + s * 8);
                uint32_t bt = dst + (2 + p) * TILE_BYTES;
                TMA_LOAD_3D(bt,        &tma_b, k0, c0,       p, sb + s * 8);
                TMA_LOAD_3D(bt + 8192, &tma_b, k0, NHQ + c0, p, sb + s * 8);
            }
        }
    }

    // ---------------- epilogue: Q/K tiles to smem, ksum, CTA-local logit partials ----------------
    float* fsm = reinterpret_cast<float*>(smem);
    float* smQ = fsm;                 // [128][66]
    float* smK = fsm + 128 * 66;      // [128][66]
    float* smS = fsm + 2 * 128 * 66;  // [4][64] per-batch ksum

    const bool isK = (wc >= 2);
    const float* __restrict__ bias = isK ? bk : bq;
    float* dst = isK ? smK : smQ;

#pragma unroll
    for (int mt = 0; mt < 4; mt++) {
        int r0 = wr * 64 + mt * 16 + g;        // local row
        int r1 = r0 + 8;
        float m0 = (float)mask[tileR + r0];
        float m1 = (float)mask[tileR + r1];
#pragma unroll
        for (int nt = 0; nt < 4; nt++) {
            int cl = (wc & 1) * 32 + nt * 8 + t * 2;   // local col 0..62
            float b0 = bias[c0 + cl], b1 = bias[c0 + cl + 1];
            float v0 = acc0[mt][nt][0] + acc1[mt][nt][0] * LO_INV;
            float v1 = acc0[mt][nt][1] + acc1[mt][nt][1] * LO_INV;
            float v2 = acc0[mt][nt][2] + acc1[mt][nt][2] * LO_INV;
            float v3 = acc0[mt][nt][3] + acc1[mt][nt][3] * LO_INV;
            float2 o0, o1;
            o0.x = (v0 + b0) * m0;
            o0.y = (v1 + b1) * m0;
            o1.x = (v2 + b0) * m1;
            o1.y = (v3 + b1) * m1;
            *reinterpret_cast<float2*>(&dst[r0 * 66 + cl]) = o0;
            *reinterpret_cast<float2*>(&dst[r1 * 66 + cl]) = o1;
        }
    }
    __syncthreads();

    // per-batch ksum over local K tile (4 batches of 32 rows)
    {
        int batch = tid >> 6;          // 0..3
        int col   = tid & 63;          // 0..63
        float s = 0.f;
#pragma unroll
        for (int i = 0; i < 32; i++)
            s += smK[(batch * 32 + i) * 66 + col];
        smS[batch * 64 + col] = s;
    }
    __syncthreads();

    // logit partial per row: sum_c Q[x,c] * (ksum_b[c] - K[x,c])
    if (tid < 128) {
        int row = tid;
        int bl = row >> 5;
        float s = 0.f;
#pragma unroll
        for (int cc = 0; cc < 64; cc++)
            s += smQ[row * 66 + cc] * (smS[bl * 64 + cc] - smK[row * 66 + cc]);
        g_lpart[blockIdx.x * ROWS + tileR + row] = s;
    }
}

// ---------------- kernel 3: softmax (32 blocks x 32 threads) ----------------
__global__ void softmax_kernel(const int* __restrict__ mask, float* __restrict__ out)
{
    int b = blockIdx.x;
    int x = threadIdx.x;
    int row = b * AA + x;
    float l = 0.f;
#pragma unroll
    for (int ct = 0; ct < 16; ct++)
        l += g_lpart[ct * ROWS + row];
    float m = (float)mask[row];
    l += (1.0f - m) * -100000.0f;
    float mx = l;
#pragma unroll
    for (int o = 16; o > 0; o >>= 1) mx = fmaxf(mx, __shfl_xor_sync(0xffffffffu, mx, o));
    float e = expf(l - mx);
    float se = e;
#pragma unroll
    for (int o = 16; o > 0; o >>= 1) se += __shfl_xor_sync(0xffffffffu, se, o);
    out[row] = e / se;
}

// ---------------- host: tensor map construction ----------------
typedef CUresult (*EncodeTiledFn)(
    CUtensorMap*, CUtensorMapDataType, cuuint32_t, void*,
    const cuuint64_t*, const cuuint64_t*, const cuuint32_t*, const cuuint32_t*,
    CUtensorMapInterleave, CUtensorMapSwizzle, CUtensorMapL2promotion, CUtensorMapFloatOOBfill);

extern "C" void kernel_launch(void* const* d_in, const int* in_sizes, int n_in,
                              void* d_out, int out_size)
{
    const float* enc  = (const float*)d_in[0];
    const int*   mask = (const int*)  d_in[1];
    const float* wq   = (const float*)d_in[2];
    const float* bq   = (const float*)d_in[3];
    const float* wk   = (const float*)d_in[4];
    const float* bk   = (const float*)d_in[5];
    float* out = (float*)d_out;

    cudaFuncSetAttribute(gemm_mma_kernel, cudaFuncAttributeMaxDynamicSharedMemorySize, SMEM_TOTAL);

    void* fn = nullptr;
    cudaDriverEntryPointQueryResult qr;
    cudaGetDriverEntryPointByVersion("cuTensorMapEncodeTiled", &fn, 12000,
                                     cudaEnableDefault, &qr);
    EncodeTiledFn encode = (EncodeTiledFn)fn;

    void *pA = nullptr, *pB = nullptr;
    cudaGetSymbolAddress(&pA, g_A2);
    cudaGetSymbolAddress(&pB, g_B2);

    CUtensorMap tmaA, tmaB;
    {
        cuuint64_t dims[3]    = {DD, ROWS, 2};
        cuuint64_t strides[2] = {DD * 2ull, (cuuint64_t)ROWS * DD * 2ull};
        cuuint32_t box[3]     = {KC, 128, 1};
        cuuint32_t es[3]      = {1, 1, 1};
        encode(&tmaA, CU_TENSOR_MAP_DATA_TYPE_UINT16, 3, pA, dims, strides, box, es,
               CU_TENSOR_MAP_INTERLEAVE_NONE, CU_TENSOR_MAP_SWIZZLE_128B,
               CU_TENSOR_MAP_L2_PROMOTION_L2_128B, CU_TENSOR_MAP_FLOAT_OOB_FILL_NONE);
    }
    {
        cuuint64_t dims[3]    = {DD, COLS2, 2};
        cuuint64_t strides[2] = {DD * 2ull, (cuuint64_t)COLS2 * DD * 2ull};
        cuuint32_t box[3]     = {KC, 64, 1};
        cuuint32_t es[3]      = {1, 1, 1};
        encode(&tmaB, CU_TENSOR_MAP_DATA_TYPE_UINT16, 3, pB, dims, strides, box, es,
               CU_TENSOR_MAP_INTERLEAVE_NONE, CU_TENSOR_MAP_SWIZZLE_128B,
               CU_TENSOR_MAP_L2_PROMOTION_L2_128B, CU_TENSOR_MAP_FLOAT_OOB_FILL_NONE);
    }

    split_all_kernel<<<ROWS + 1024, 256>>>(enc, wq, wk);
    gemm_mma_kernel<<<dim3(16, 8), 256, SMEM_TOTAL>>>(tmaA, tmaB, bq, bk, mask);
    softmax_kernel<<<BB, 32>>>(mask, out);
}